// round 12
// baseline (speedup 1.0000x reference)
#include <cuda_runtime.h>
#include <cuda_bf16.h>
#include <math.h>
#include <stdint.h>

#define BZ 32
#define HH 56
#define WW 56
#define DIM 256
#define HEADS 8
#define WS 7
#define SHIFT 3
#define NTOK 49
#define NWIN 64
#define HEAD_DIM 32
#define HIDDEN 1024
#define MTOT (BZ*HH*WW)    // 100352 rows

typedef __nv_bfloat16 bf16;

// ---------------- scratch ----------------------------------------------------
__device__ bf16  g_hwin[(size_t)MTOT * DIM];
__device__ bf16  g_qkv [(size_t)MTOT * 3 * DIM];
__device__ bf16  g_attn[(size_t)MTOT * DIM];
__device__ float g_x1  [(size_t)MTOT * DIM];
__device__ bf16  g_h2  [(size_t)MTOT * HIDDEN];
__device__ bf16  g_wqkv[3 * DIM * DIM];
__device__ bf16  g_wproj[DIM * DIM];
__device__ bf16  g_wfc1[HIDDEN * DIM];
__device__ bf16  g_wfc2[DIM * HIDDEN];
__device__ bf16  g_comb[64 * 8 * 64 * 64];

__device__ __forceinline__ int remap_row(int m) {
    int b    = m / (NWIN * NTOK);
    int rem  = m - b * (NWIN * NTOK);
    int wimg = rem / NTOK;
    int n    = rem - wimg * NTOK;
    int hh = (wimg >> 3) * WS + n / WS + SHIFT; if (hh >= HH) hh -= HH;
    int ww = (wimg & 7) * WS + n % WS + SHIFT;  if (ww >= WW) ww -= WW;
    return b * (HH * WW) + hh * WW + ww;
}

// ---------------- ptx helpers -------------------------------------------------
__device__ __forceinline__ uint32_t smem_u32(const void* p) {
    return (uint32_t)__cvta_generic_to_shared(p);
}
__device__ __forceinline__ void cp16(uint32_t dst, const void* src) {
    asm volatile("cp.async.cg.shared.global [%0], [%1], 16;\n" :: "r"(dst), "l"(src));
}
__device__ __forceinline__ void cp_commit() { asm volatile("cp.async.commit_group;\n"); }
template<int N> __device__ __forceinline__ void cp_wait() {
    asm volatile("cp.async.wait_group %0;\n" :: "n"(N));
}
__device__ __forceinline__ void ldsm4(uint32_t* r, uint32_t addr) {
    asm volatile("ldmatrix.sync.aligned.m8n8.x4.shared.b16 {%0,%1,%2,%3}, [%4];"
                 : "=r"(r[0]), "=r"(r[1]), "=r"(r[2]), "=r"(r[3]) : "r"(addr));
}
__device__ __forceinline__ void mma_bf16(float* d, const uint32_t* a, const uint32_t* b) {
    asm volatile(
        "mma.sync.aligned.m16n8k16.row.col.f32.bf16.bf16.f32 "
        "{%0,%1,%2,%3}, {%4,%5,%6,%7}, {%8,%9}, {%0,%1,%2,%3};\n"
        : "+f"(d[0]), "+f"(d[1]), "+f"(d[2]), "+f"(d[3])
        : "r"(a[0]), "r"(a[1]), "r"(a[2]), "r"(a[3]), "r"(b[0]), "r"(b[1]));
}
__device__ __forceinline__ uint32_t pack_bf16x2(float a, float b) {
    __nv_bfloat162 h;
    h.x = __float2bfloat16(a); h.y = __float2bfloat16(b);
    return *(uint32_t*)&h;
}

// ---------------- fp32 -> bf16 weight convert (fused, 4 segs) -----------------
__global__ void cvt4_kernel(const float* s0, bf16* d0, int n0,
                            const float* s1, bf16* d1, int n1,
                            const float* s2, bf16* d2, int n2,
                            const float* s3, bf16* d3, int n3) {
    const float* s; bf16* d; int n;
    switch (blockIdx.y) {
        case 0: s = s0; d = d0; n = n0; break;
        case 1: s = s1; d = d1; n = n1; break;
        case 2: s = s2; d = d2; n = n2; break;
        default: s = s3; d = d3; n = n3; break;
    }
    int i = (blockIdx.x * blockDim.x + threadIdx.x) * 4;
    if (i < n) {
        float4 v = *(const float4*)(s + i);
        __nv_bfloat162 p0 = {__float2bfloat16(v.x), __float2bfloat16(v.y)};
        __nv_bfloat162 p1 = {__float2bfloat16(v.z), __float2bfloat16(v.w)};
        *(__nv_bfloat162*)(d + i)     = p0;
        *(__nv_bfloat162*)(d + i + 2) = p1;
    }
}

// ---------------- comb bias precompute ---------------------------------------
__global__ void comb_kernel(const float* __restrict__ rpb,
                            const int* __restrict__ relix,
                            const float* __restrict__ mask,
                            bf16* __restrict__ comb) {
    int w = blockIdx.x, h = blockIdx.y;
    const float* mw = mask + w * (NTOK * NTOK);
    size_t base = ((size_t)(w * 8 + h)) << 12;
    for (int e = threadIdx.x; e < 4096; e += 256) {
        int n = e >> 6, m = e & 63;
        float v = -1e30f;
        if (n < NTOK && m < NTOK)
            v = rpb[relix[n * NTOK + m] * HEADS + h] + mw[n * NTOK + m];
        comb[base + e] = __float2bfloat16(v);
    }
}

// ---------------- LayerNorm (warp per row, bf16 out) -------------------------
template<bool SHIFTMAP>
__global__ void __launch_bounds__(256) ln_kernel(const float* __restrict__ x,
                                                 const float* __restrict__ gw,
                                                 const float* __restrict__ gb,
                                                 bf16* __restrict__ out) {
    int warp = threadIdx.x >> 5, lane = threadIdx.x & 31;
    int m = blockIdx.x * 8 + warp;
    const float* xr;
    if (SHIFTMAP) {
        int r = remap_row(m);
        xr = x + (size_t)r * DIM;
    } else {
        xr = x + (size_t)m * DIM;
    }
    float4 v0 = *(const float4*)(xr + lane * 4);
    float4 v1 = *(const float4*)(xr + 128 + lane * 4);
    float s  = v0.x + v0.y + v0.z + v0.w + v1.x + v1.y + v1.z + v1.w;
    float sq = v0.x*v0.x + v0.y*v0.y + v0.z*v0.z + v0.w*v0.w
             + v1.x*v1.x + v1.y*v1.y + v1.z*v1.z + v1.w*v1.w;
    #pragma unroll
    for (int o = 16; o; o >>= 1) {
        s  += __shfl_xor_sync(0xffffffffu, s,  o);
        sq += __shfl_xor_sync(0xffffffffu, sq, o);
    }
    float mu  = s * (1.0f / DIM);
    float var = sq * (1.0f / DIM) - mu * mu;
    float rs  = rsqrtf(var + 1e-5f);
    float4 w0 = *(const float4*)(gw + lane * 4);
    float4 w1 = *(const float4*)(gw + 128 + lane * 4);
    float4 b0 = *(const float4*)(gb + lane * 4);
    float4 b1 = *(const float4*)(gb + 128 + lane * 4);
    bf16* orow = out + (size_t)m * DIM;
    __nv_bfloat162 p;
    p = {__float2bfloat16((v0.x-mu)*rs*w0.x+b0.x), __float2bfloat16((v0.y-mu)*rs*w0.y+b0.y)};
    *(__nv_bfloat162*)(orow + lane*4)     = p;
    p = {__float2bfloat16((v0.z-mu)*rs*w0.z+b0.z), __float2bfloat16((v0.w-mu)*rs*w0.w+b0.w)};
    *(__nv_bfloat162*)(orow + lane*4 + 2) = p;
    p = {__float2bfloat16((v1.x-mu)*rs*w1.x+b1.x), __float2bfloat16((v1.y-mu)*rs*w1.y+b1.y)};
    *(__nv_bfloat162*)(orow + 128 + lane*4)     = p;
    p = {__float2bfloat16((v1.z-mu)*rs*w1.z+b1.z), __float2bfloat16((v1.w-mu)*rs*w1.w+b1.w)};
    *(__nv_bfloat162*)(orow + 128 + lane*4 + 2) = p;
}

// ============ persistent-B GEMM (K=256): B slice resident in smem =============
// 256 threads, 8 warps in 2(m) x 4(n) grid; warp tile 64x64.
#define PA_SROW 144
#define PA_STAGE (128 * PA_SROW)        // 18432
#define PB_SROW 528
#define PB_OFF (3 * PA_STAGE)           // 55296
#define PSMEM (PB_OFF + 256 * PB_SROW)  // 190464

template<int EPI>
__global__ void __launch_bounds__(256, 1) pgemm(const bf16* __restrict__ A,
                                               const bf16* __restrict__ Bm,
                                               const float* __restrict__ bias,
                                               void* __restrict__ Cv,
                                               int M, int N,
                                               const float* __restrict__ res,
                                               int GY) {
    const int K = 256;
    extern __shared__ __align__(16) char smem[];
    uint32_t sbase = smem_u32(smem);
    int tid = threadIdx.x;
    int warp = tid >> 5, lane = tid & 31;
    int bn = blockIdx.x, gy = blockIdx.y;
    int warpM = (warp & 1) * 64;
    int warpN = (warp >> 1) * 64;
    int r = lane >> 2, c = lane & 3;
    int mt = M >> 7;

    uint32_t sB = sbase + PB_OFF;
    // one-time B slice load: 256 rows x 256 cols bf16 (8192 chunks / 256 thr)
    {
        const bf16* Bbase = Bm + (size_t)(bn * 256) * K;
        #pragma unroll
        for (int rpt = 0; rpt < 32; rpt++) {
            int ch = tid + rpt * 256;
            int row = ch >> 5, col = ch & 31;
            cp16(sB + row * PB_SROW + col * 16, Bbase + (size_t)row * K + col * 8);
        }
    }
    cp_commit();

    uint32_t aoff = (uint32_t)((lane & 15) * PA_SROW + (lane >> 4) * 16);
    uint32_t boff = (uint32_t)(((lane & 7) + ((lane >> 4) << 3)) * PB_SROW
                               + ((lane & 8) ? 16 : 0));

    int ntiles = (mt - gy + GY - 1) / GY;
    int nj = ntiles * 4;

#define FILLA(s, j) do { \
    const bf16* Ab = A + (size_t)(gy + ((j) >> 2) * GY) * 128 * K + ((j) & 3) * 64; \
    uint32_t as = sbase + (s) * PA_STAGE; \
    _Pragma("unroll") \
    for (int rpt = 0; rpt < 4; rpt++) { \
        int ch = tid + rpt * 256; \
        int row = ch >> 3, col = ch & 7; \
        cp16(as + row * PA_SROW + col * 16, Ab + (size_t)row * K + col * 8); \
    } \
} while (0)

    FILLA(0, 0);
    cp_commit();
    if (nj > 1) FILLA(1, 1);
    cp_commit();

    for (int t = 0; t < ntiles; t++) {
        int bm = gy + t * GY;
        float acc[4][8][4];
        #pragma unroll
        for (int mi = 0; mi < 4; mi++)
            #pragma unroll
            for (int ni = 0; ni < 8; ni++)
                #pragma unroll
                for (int q = 0; q < 4; q++) acc[mi][ni][q] = 0.0f;

        #pragma unroll
        for (int s4 = 0; s4 < 4; s4++) {
            int j = t * 4 + s4;
            cp_wait<1>();
            __syncthreads();
            if (j + 2 < nj) FILLA((j + 2) % 3, j + 2);
            cp_commit();

            uint32_t As = sbase + (j % 3) * PA_STAGE;
            #pragma unroll
            for (int kk = 0; kk < 4; kk++) {
                int k16 = s4 * 4 + kk;
                uint32_t af[4][4], bfr[4][4];
                #pragma unroll
                for (int mi = 0; mi < 4; mi++)
                    ldsm4(af[mi], As + (uint32_t)((warpM + mi * 16) * PA_SROW + kk * 32) + aoff);
                #pragma unroll
                for (int p = 0; p < 4; p++)
                    ldsm4(bfr[p], sB + (uint32_t)((warpN + p * 16) * PB_SROW + k16 * 32) + boff);
                #pragma unroll
                for (int mi = 0; mi < 4; mi++)
                    #pragma unroll
                    for (int ni = 0; ni < 8; ni++)
                        mma_bf16(acc[mi][ni], af[mi], &bfr[ni >> 1][(ni & 1) * 2]);
            }
        }

        // epilogue for this tile
        #pragma unroll
        for (int mi = 0; mi < 4; mi++) {
            #pragma unroll
            for (int half = 0; half < 2; half++) {
                int row = bm * 128 + warpM + mi * 16 + r + half * 8;
                int orow = row;
                if (EPI == 2) orow = remap_row(row);
                const float* rr = (EPI == 2 || EPI == 3) ? res + (size_t)orow * N : nullptr;
                #pragma unroll
                for (int ni = 0; ni < 8; ni++) {
                    int col = bn * 256 + warpN + ni * 8 + 2 * c;
                    float v0 = acc[mi][ni][half * 2 + 0] + bias[col];
                    float v1 = acc[mi][ni][half * 2 + 1] + bias[col + 1];
                    if (EPI == 1) {
                        v0 = 0.5f * v0 * (1.0f + erff(v0 * 0.70710678118654752f));
                        v1 = 0.5f * v1 * (1.0f + erff(v1 * 0.70710678118654752f));
                    }
                    if (EPI == 2 || EPI == 3) {
                        v0 += rr[col];
                        v1 += rr[col + 1];
                    }
                    if (EPI == 0 || EPI == 1) {
                        bf16* cp = (bf16*)Cv + (size_t)orow * N;
                        __nv_bfloat162 pk = {__float2bfloat16(v0), __float2bfloat16(v1)};
                        *(__nv_bfloat162*)(cp + col) = pk;
                    } else {
                        float* cp = (float*)Cv + (size_t)orow * N;
                        *(float2*)(cp + col) = make_float2(v0, v1);
                    }
                }
            }
        }
    }
#undef FILLA
}

// ---------------- streaming GEMM (for fc2, K=1024) ---------------------------
#define SROW 144
#define ASTAGE (128 * SROW)
#define BSTAGE (256 * SROW)
#define STAGEB (ASTAGE + BSTAGE)
#define NSTAGE 3
#define SMEM_DYN (NSTAGE * STAGEB)  // 165888
#define GTHREADS 512

template<int EPI>
__global__ void __launch_bounds__(GTHREADS, 1) bgemm(const bf16* __restrict__ A,
                                                    const bf16* __restrict__ Bm,
                                                    const float* __restrict__ bias,
                                                    void* __restrict__ Cv,
                                                    int M, int N, int K,
                                                    const float* __restrict__ res) {
    extern __shared__ __align__(16) char smem[];
    uint32_t sbase = smem_u32(smem);
    int tid = threadIdx.x;
    int bn = blockIdx.x, bm = blockIdx.y;
    int warp = tid >> 5, lane = tid & 31;
    int warpM = (warp & 3) * 32;
    int warpN = (warp >> 2) * 64;
    int r = lane >> 2, c = lane & 3;

    int arw[2], acc_[2], brw[4], bcc[4];
    #pragma unroll
    for (int rpt = 0; rpt < 2; rpt++) {
        int ch = tid + rpt * GTHREADS;
        arw[rpt] = ch >> 3; acc_[rpt] = ch & 7;
    }
    #pragma unroll
    for (int rpt = 0; rpt < 4; rpt++) {
        int ch = tid + rpt * GTHREADS;
        brw[rpt] = ch >> 3; bcc[rpt] = ch & 7;
    }
    const bf16* Abase = A  + (size_t)(bm * 128) * K;
    const bf16* Bbase = Bm + (size_t)(bn * 256) * K;

    uint32_t aoff = (uint32_t)((lane & 15) * SROW + (lane >> 4) * 16);
    uint32_t boff = (uint32_t)(((lane & 7) + ((lane >> 4) << 3)) * SROW + ((lane & 8) ? 16 : 0));

    float acc[2][8][4];
    #pragma unroll
    for (int mi = 0; mi < 2; mi++)
        #pragma unroll
        for (int ni = 0; ni < 8; ni++)
            #pragma unroll
            for (int t = 0; t < 4; t++) acc[mi][ni][t] = 0.0f;

#define FILL(s, k0) do { \
    uint32_t ab = sbase + (s) * STAGEB; \
    uint32_t bb = ab + ASTAGE; \
    _Pragma("unroll") \
    for (int rpt = 0; rpt < 2; rpt++) \
        cp16(ab + arw[rpt] * SROW + acc_[rpt] * 16, \
             Abase + (size_t)arw[rpt] * K + (k0) + acc_[rpt] * 8); \
    _Pragma("unroll") \
    for (int rpt = 0; rpt < 4; rpt++) \
        cp16(bb + brw[rpt] * SROW + bcc[rpt] * 16, \
             Bbase + (size_t)brw[rpt] * K + (k0) + bcc[rpt] * 8); \
} while (0)

    int nk = K >> 6;
    FILL(0, 0);  cp_commit();
    FILL(1, 64); cp_commit();

    int stage = 0, fstage = 2;
    for (int i = 0; i < nk; i++) {
        cp_wait<1>();
        __syncthreads();
        if (i + 2 < nk) {
            FILL(fstage, (i + 2) * 64);
        }
        cp_commit();

        uint32_t Ab = sbase + stage * STAGEB;
        uint32_t Bb = Ab + ASTAGE;

        #pragma unroll
        for (int kk = 0; kk < 4; kk++) {
            uint32_t af[2][4], bfr[4][4];
            #pragma unroll
            for (int mi = 0; mi < 2; mi++)
                ldsm4(af[mi], Ab + (uint32_t)((warpM + mi * 16) * SROW + kk * 32) + aoff);
            #pragma unroll
            for (int p = 0; p < 4; p++)
                ldsm4(bfr[p], Bb + (uint32_t)((warpN + p * 16) * SROW + kk * 32) + boff);
            #pragma unroll
            for (int mi = 0; mi < 2; mi++)
                #pragma unroll
                for (int ni = 0; ni < 8; ni++)
                    mma_bf16(acc[mi][ni], af[mi], &bfr[ni >> 1][(ni & 1) * 2]);
        }

        stage = (stage + 1 == NSTAGE) ? 0 : stage + 1;
        fstage = (fstage + 1 == NSTAGE) ? 0 : fstage + 1;
    }

    #pragma unroll
    for (int mi = 0; mi < 2; mi++) {
        #pragma unroll
        for (int half = 0; half < 2; half++) {
            int row = bm * 128 + warpM + mi * 16 + r + half * 8;
            int orow = row;
            if (EPI == 2) orow = remap_row(row);
            const float* rr = (EPI == 2 || EPI == 3) ? res + (size_t)orow * N : nullptr;
            #pragma unroll
            for (int ni = 0; ni < 8; ni++) {
                int col = bn * 256 + warpN + ni * 8 + 2 * c;
                float v0 = acc[mi][ni][half * 2 + 0] + bias[col];
                float v1 = acc[mi][ni][half * 2 + 1] + bias[col + 1];
                if (EPI == 1) {
                    v0 = 0.5f * v0 * (1.0f + erff(v0 * 0.70710678118654752f));
                    v1 = 0.5f * v1 * (1.0f + erff(v1 * 0.70710678118654752f));
                }
                if (EPI == 2 || EPI == 3) {
                    v0 += rr[col];
                    v1 += rr[col + 1];
                }
                if (EPI == 0 || EPI == 1) {
                    bf16* cp = (bf16*)Cv + (size_t)orow * N;
                    __nv_bfloat162 pk = {__float2bfloat16(v0), __float2bfloat16(v1)};
                    *(__nv_bfloat162*)(cp + col) = pk;
                } else {
                    float* cp = (float*)Cv + (size_t)orow * N;
                    *(float2*)(cp + col) = make_float2(v0, v1);
                }
            }
        }
    }
#undef FILL
}

// ---------------- tensor-core windowed attention ------------------------------
__global__ void __launch_bounds__(256) attn_tc(const bf16* __restrict__ qkv,
                                               const bf16* __restrict__ comb,
                                               bf16* __restrict__ out) {
    __shared__ __align__(16) bf16 sQ[2][64 * 40];
    __shared__ __align__(16) bf16 sK[2][64 * 40];
    __shared__ __align__(16) bf16 sVT[2][32 * 72];
    __shared__ __align__(16) bf16 sB[2][64 * 72];

    int tid = threadIdx.x;
    int win = blockIdx.x;
    int hg  = blockIdx.y * 2;
    int w64 = win & 63;

    uint32_t* vz = (uint32_t*)sVT;
    for (int i = tid; i < 2 * 32 * 72 / 2; i += 256) vz[i] = 0;
    for (int i = tid; i < 600; i += 256) {
        int h = i / 300, rm = i % 300;
        int row = 49 + rm / 20, w = rm % 20;
        ((uint32_t*)sQ)[h * 1280 + row * 20 + w] = 0;
        ((uint32_t*)sK)[h * 1280 + row * 20 + w] = 0;
    }
    __syncthreads();

    for (int i = tid; i < 392; i += 256) {
        int h = i / 196, rm = i % 196;
        int tok = rm >> 2, ch = rm & 3;
        const bf16* src = qkv + (size_t)(win * 49 + tok) * 768 + (hg + h) * 32 + ch * 8;
        *(uint4*)((char*)sQ + h * 5120 + tok * 80 + ch * 16) = *(const uint4*)src;
        *(uint4*)((char*)sK + h * 5120 + tok * 80 + ch * 16) = *(const uint4*)(src + 256);
    }
    for (int i = tid; i < 1568; i += 256) {
        int h = i / 784, rm = i % 784;
        int tok = rm / 16, dp = (rm % 16) * 2;
        __nv_bfloat162 v = *(const __nv_bfloat162*)(qkv + (size_t)(win * 49 + tok) * 768
                                                    + 512 + (hg + h) * 32 + dp);
        *(bf16*)((char*)sVT + h * 4608 + dp * 144 + tok * 2)       = v.x;
        *(bf16*)((char*)sVT + h * 4608 + (dp + 1) * 144 + tok * 2) = v.y;
    }
    for (int i = tid; i < 1024; i += 256) {
        int h = i >> 9, rm = i & 511;
        int n = rm >> 3, ch = rm & 7;
        const bf16* src = comb + (((size_t)((w64 * 8 + hg + h) * 64 + n)) << 6) + ch * 8;
        *(uint4*)((char*)sB + h * 9216 + n * 144 + ch * 16) = *(const uint4*)src;
    }
    __syncthreads();

    int warp = tid >> 5, lane = tid & 31;
    int head = warp >> 2;
    int rowbase = (warp & 3) * 16;

    uint32_t Qb = smem_u32(sQ) + head * 5120;
    uint32_t Kb = smem_u32(sK) + head * 5120;
    uint32_t Vb = smem_u32(sVT) + head * 4608;
    uint32_t Bb = smem_u32(sB) + head * 9216;

    uint32_t aoff80  = (uint32_t)((lane & 15) * 80 + (lane >> 4) * 16);
    uint32_t aoff144 = (uint32_t)((lane & 15) * 144 + (lane >> 4) * 16);
    uint32_t boff80  = (uint32_t)(((lane & 7) + ((lane >> 4) << 3)) * 80 + ((lane & 8) ? 16 : 0));
    uint32_t boff144 = (uint32_t)(((lane & 7) + ((lane >> 4) << 3)) * 144 + ((lane & 8) ? 16 : 0));

    float sacc[8][4];
    #pragma unroll
    for (int ni = 0; ni < 8; ni++)
        #pragma unroll
        for (int t = 0; t < 4; t++) sacc[ni][t] = 0.0f;

    #pragma unroll
    for (int ks = 0; ks < 2; ks++) {
        uint32_t aq[4], bk[4][4];
        ldsm4(aq, Qb + (uint32_t)(rowbase * 80 + ks * 32) + aoff80);
        #pragma unroll
        for (int p = 0; p < 4; p++)
            ldsm4(bk[p], Kb + (uint32_t)(p * 16 * 80 + ks * 32) + boff80);
        #pragma unroll
        for (int ni = 0; ni < 8; ni++)
            mma_bf16(sacc[ni], aq, &bk[ni >> 1][(ni & 1) * 2]);
    }

    const float scale = 0.17677669529663687f;
    #pragma unroll
    for (int cg = 0; cg < 4; cg++) {
        uint32_t bb[4];
        ldsm4(bb, Bb + (uint32_t)(rowbase * 144 + cg * 32) + aoff144);
        float2 f;
        f = __bfloat1622float2(*(__nv_bfloat162*)&bb[0]);
        sacc[2*cg][0] = sacc[2*cg][0] * scale + f.x;
        sacc[2*cg][1] = sacc[2*cg][1] * scale + f.y;
        f = __bfloat1622float2(*(__nv_bfloat162*)&bb[1]);
        sacc[2*cg][2] = sacc[2*cg][2] * scale + f.x;
        sacc[2*cg][3] = sacc[2*cg][3] * scale + f.y;
        f = __bfloat1622float2(*(__nv_bfloat162*)&bb[2]);
        sacc[2*cg+1][0] = sacc[2*cg+1][0] * scale + f.x;
        sacc[2*cg+1][1] = sacc[2*cg+1][1] * scale + f.y;
        f = __bfloat1622float2(*(__nv_bfloat162*)&bb[3]);
        sacc[2*cg+1][2] = sacc[2*cg+1][2] * scale + f.x;
        sacc[2*cg+1][3] = sacc[2*cg+1][3] * scale + f.y;
    }

    #pragma unroll
    for (int hf = 0; hf < 2; hf++) {
        int i0 = hf * 2;
        float mx = -1e30f;
        #pragma unroll
        for (int ni = 0; ni < 8; ni++)
            mx = fmaxf(mx, fmaxf(sacc[ni][i0], sacc[ni][i0 + 1]));
        mx = fmaxf(mx, __shfl_xor_sync(0xffffffffu, mx, 1));
        mx = fmaxf(mx, __shfl_xor_sync(0xffffffffu, mx, 2));
        float sum = 0.0f;
        #pragma unroll
        for (int ni = 0; ni < 8; ni++) {
            float e0 = expf(sacc[ni][i0] - mx);
            float e1 = expf(sacc[ni][i0 + 1] - mx);
            sacc[ni][i0] = e0; sacc[ni][i0 + 1] = e1;
            sum += e0 + e1;
        }
        sum += __shfl_xor_sync(0xffffffffu, sum, 1);
        sum += __shfl_xor_sync(0xffffffffu, sum, 2);
        float inv = 1.0f / sum;
        #pragma unroll
        for (int ni = 0; ni < 8; ni++) {
            sacc[ni][i0] *= inv; sacc[ni][i0 + 1] *= inv;
        }
    }

    uint32_t pa[4][4];
    #pragma unroll
    for (int ks = 0; ks < 4; ks++) {
        pa[ks][0] = pack_bf16x2(sacc[2*ks][0],   sacc[2*ks][1]);
        pa[ks][1] = pack_bf16x2(sacc[2*ks][2],   sacc[2*ks][3]);
        pa[ks][2] = pack_bf16x2(sacc[2*ks+1][0], sacc[2*ks+1][1]);
        pa[ks][3] = pack_bf16x2(sacc[2*ks+1][2], sacc[2*ks+1][3]);
    }

    float oacc[4][4];
    #pragma unroll
    for (int ni = 0; ni < 4; ni++)
        #pragma unroll
        for (int t = 0; t < 4; t++) oacc[ni][t] = 0.0f;

    #pragma unroll
    for (int ks = 0; ks < 4; ks++) {
        uint32_t bv[2][4];
        #pragma unroll
        for (int p = 0; p < 2; p++)
            ldsm4(bv[p], Vb + (uint32_t)(p * 16 * 144 + ks * 32) + boff144);
        #pragma unroll
        for (int ni = 0; ni < 4; ni++)
            mma_bf16(oacc[ni], pa[ks], &bv[ni >> 1][(ni & 1) * 2]);
    }

    int gh = hg + head;
    int r0 = rowbase + (lane >> 2);
    #pragma unroll
    for (int ni = 0; ni < 4; ni++) {
        int col = gh * 32 + ni * 8 + (lane & 3) * 2;
        if (r0 < NTOK) {
            __nv_bfloat162 pk = {__float2bfloat16(oacc[ni][0]), __float2bfloat16(oacc[ni][1])};
            *(__nv_bfloat162*)(out + (size_t)(win * 49 + r0) * 256 + col) = pk;
        }
        if (r0 + 8 < NTOK) {
            __nv_bfloat162 pk = {__float2bfloat16(oacc[ni][2]), __float2bfloat16(oacc[ni][3])};
            *(__nv_bfloat162*)(out + (size_t)(win * 49 + r0 + 8) * 256 + col) = pk;
        }
    }
}

// ---------------- launcher ---------------------------------------------------
extern "C" void kernel_launch(void* const* d_in, const int* in_sizes, int n_in,
                              void* d_out, int out_size) {
    const float* x     = (const float*)d_in[0];
    const float* n1w   = (const float*)d_in[1];
    const float* n1b   = (const float*)d_in[2];
    const float* qkvw  = (const float*)d_in[3];
    const float* qkvb  = (const float*)d_in[4];
    const float* rpb   = (const float*)d_in[5];
    const float* projw = (const float*)d_in[6];
    const float* projb = (const float*)d_in[7];
    const float* n2w   = (const float*)d_in[8];
    const float* n2b   = (const float*)d_in[9];
    const float* fc1w  = (const float*)d_in[10];
    const float* fc1b  = (const float*)d_in[11];
    const float* fc2w  = (const float*)d_in[12];
    const float* fc2b  = (const float*)d_in[13];
    const int*   relix = (const int*)d_in[14];
    const float* amask = (const float*)d_in[15];
    float* out = (float*)d_out;

    bf16 *hwin, *qkv, *attn, *h2, *wqkv, *wproj, *wfc1, *wfc2, *comb;
    float *x1;
    cudaGetSymbolAddress((void**)&hwin, g_hwin);
    cudaGetSymbolAddress((void**)&qkv,  g_qkv);
    cudaGetSymbolAddress((void**)&attn, g_attn);
    cudaGetSymbolAddress((void**)&x1,   g_x1);
    cudaGetSymbolAddress((void**)&h2,   g_h2);
    cudaGetSymbolAddress((void**)&wqkv, g_wqkv);
    cudaGetSymbolAddress((void**)&wproj, g_wproj);
    cudaGetSymbolAddress((void**)&wfc1, g_wfc1);
    cudaGetSymbolAddress((void**)&wfc2, g_wfc2);
    cudaGetSymbolAddress((void**)&comb, g_comb);

    cudaFuncSetAttribute(pgemm<0>, cudaFuncAttributeMaxDynamicSharedMemorySize, PSMEM);
    cudaFuncSetAttribute(pgemm<1>, cudaFuncAttributeMaxDynamicSharedMemorySize, PSMEM);
    cudaFuncSetAttribute(pgemm<2>, cudaFuncAttributeMaxDynamicSharedMemorySize, PSMEM);
    cudaFuncSetAttribute(bgemm<3>, cudaFuncAttributeMaxDynamicSharedMemorySize, SMEM_DYN);

    cvt4_kernel<<<dim3(DIM * HIDDEN / 4 / 256, 4), 256>>>(
        qkvw, wqkv, 3 * DIM * DIM,
        projw, wproj, DIM * DIM,
        fc1w, wfc1, HIDDEN * DIM,
        fc2w, wfc2, DIM * HIDDEN);
    comb_kernel<<<dim3(64, 8), 256>>>(rpb, relix, amask, comb);

    // 1. LN1 + shift + window-partition (bf16 out)
    ln_kernel<true><<<MTOT / 8, 256>>>(x, n1w, n1b, hwin);
    // 2. QKV GEMM (persistent-B, 64x64 warp tiles) -> bf16
    pgemm<0><<<dim3(3, 49), 256, PSMEM>>>(hwin, wqkv, qkvb, qkv, MTOT, 3 * DIM,
                                          nullptr, 49);
    // 3. tensor-core windowed attention
    attn_tc<<<dim3(BZ * NWIN, 4), 256>>>(qkv, comb, attn);
    // 4. proj GEMM (persistent-B) + window-reverse scatter + residual -> f32
    pgemm<2><<<dim3(1, 148), 256, PSMEM>>>(attn, wproj, projb, x1, MTOT, DIM,
                                           x, 148);
    // 5. LN2 (bf16 out)
    ln_kernel<false><<<MTOT / 8, 256>>>(x1, n2w, n2b, hwin);
    // 6. FC1 + GELU (persistent-B) -> bf16
    pgemm<1><<<dim3(4, 37), 256, PSMEM>>>(hwin, wfc1, fc1b, h2, MTOT, HIDDEN,
                                          nullptr, 37);
    // 7. FC2 + residual -> out (f32)  (streaming: K=1024)
    bgemm<3><<<dim3(1, MTOT / 128), GTHREADS, SMEM_DYN>>>(h2, wfc2, fc2b, out,
                                                          MTOT, DIM, HIDDEN, x1);
}

// round 13
// speedup vs baseline: 1.1731x; 1.1731x over previous
#include <cuda_runtime.h>
#include <cuda_bf16.h>
#include <math.h>
#include <stdint.h>

#define BZ 32
#define HH 56
#define WW 56
#define DIM 256
#define HEADS 8
#define WS 7
#define SHIFT 3
#define NTOK 49
#define NWIN 64
#define HEAD_DIM 32
#define HIDDEN 1024
#define MTOT (BZ*HH*WW)    // 100352 rows

typedef __nv_bfloat16 bf16;

// ---------------- scratch ----------------------------------------------------
__device__ bf16  g_hwin[(size_t)MTOT * DIM];
__device__ bf16  g_qkv [(size_t)MTOT * 3 * DIM];
__device__ bf16  g_attn[(size_t)MTOT * DIM];
__device__ float g_x1  [(size_t)MTOT * DIM];
__device__ bf16  g_h2  [(size_t)MTOT * HIDDEN];
__device__ float g_acc [(size_t)MTOT * DIM];       // fc2 split-K partials
__device__ bf16  g_wqkv[3 * DIM * DIM];
__device__ bf16  g_wproj[DIM * DIM];
__device__ bf16  g_wfc1[HIDDEN * DIM];
__device__ bf16  g_wfc2[DIM * HIDDEN];
__device__ bf16  g_comb[64 * 8 * 64 * 64];

__device__ __forceinline__ int remap_row(int m) {
    int b    = m / (NWIN * NTOK);
    int rem  = m - b * (NWIN * NTOK);
    int wimg = rem / NTOK;
    int n    = rem - wimg * NTOK;
    int hh = (wimg >> 3) * WS + n / WS + SHIFT; if (hh >= HH) hh -= HH;
    int ww = (wimg & 7) * WS + n % WS + SHIFT;  if (ww >= WW) ww -= WW;
    return b * (HH * WW) + hh * WW + ww;
}

// ---------------- ptx helpers -------------------------------------------------
__device__ __forceinline__ uint32_t smem_u32(const void* p) {
    return (uint32_t)__cvta_generic_to_shared(p);
}
__device__ __forceinline__ void cp16(uint32_t dst, const void* src) {
    asm volatile("cp.async.cg.shared.global [%0], [%1], 16;\n" :: "r"(dst), "l"(src));
}
__device__ __forceinline__ void cp_commit() { asm volatile("cp.async.commit_group;\n"); }
template<int N> __device__ __forceinline__ void cp_wait() {
    asm volatile("cp.async.wait_group %0;\n" :: "n"(N));
}
__device__ __forceinline__ void ldsm4(uint32_t* r, uint32_t addr) {
    asm volatile("ldmatrix.sync.aligned.m8n8.x4.shared.b16 {%0,%1,%2,%3}, [%4];"
                 : "=r"(r[0]), "=r"(r[1]), "=r"(r[2]), "=r"(r[3]) : "r"(addr));
}
__device__ __forceinline__ void mma_bf16(float* d, const uint32_t* a, const uint32_t* b) {
    asm volatile(
        "mma.sync.aligned.m16n8k16.row.col.f32.bf16.bf16.f32 "
        "{%0,%1,%2,%3}, {%4,%5,%6,%7}, {%8,%9}, {%0,%1,%2,%3};\n"
        : "+f"(d[0]), "+f"(d[1]), "+f"(d[2]), "+f"(d[3])
        : "r"(a[0]), "r"(a[1]), "r"(a[2]), "r"(a[3]), "r"(b[0]), "r"(b[1]));
}
__device__ __forceinline__ uint32_t pack_bf16x2(float a, float b) {
    __nv_bfloat162 h;
    h.x = __float2bfloat16(a); h.y = __float2bfloat16(b);
    return *(uint32_t*)&h;
}

// ---------------- fp32 -> bf16 weight convert (fused, 4 segs) -----------------
__global__ void cvt4_kernel(const float* s0, bf16* d0, int n0,
                            const float* s1, bf16* d1, int n1,
                            const float* s2, bf16* d2, int n2,
                            const float* s3, bf16* d3, int n3) {
    const float* s; bf16* d; int n;
    switch (blockIdx.y) {
        case 0: s = s0; d = d0; n = n0; break;
        case 1: s = s1; d = d1; n = n1; break;
        case 2: s = s2; d = d2; n = n2; break;
        default: s = s3; d = d3; n = n3; break;
    }
    int i = (blockIdx.x * blockDim.x + threadIdx.x) * 4;
    if (i < n) {
        float4 v = *(const float4*)(s + i);
        __nv_bfloat162 p0 = {__float2bfloat16(v.x), __float2bfloat16(v.y)};
        __nv_bfloat162 p1 = {__float2bfloat16(v.z), __float2bfloat16(v.w)};
        *(__nv_bfloat162*)(d + i)     = p0;
        *(__nv_bfloat162*)(d + i + 2) = p1;
    }
}

// ---------------- comb bias precompute ---------------------------------------
__global__ void comb_kernel(const float* __restrict__ rpb,
                            const int* __restrict__ relix,
                            const float* __restrict__ mask,
                            bf16* __restrict__ comb) {
    int w = blockIdx.x, h = blockIdx.y;
    const float* mw = mask + w * (NTOK * NTOK);
    size_t base = ((size_t)(w * 8 + h)) << 12;
    for (int e = threadIdx.x; e < 4096; e += 256) {
        int n = e >> 6, m = e & 63;
        float v = -1e30f;
        if (n < NTOK && m < NTOK)
            v = rpb[relix[n * NTOK + m] * HEADS + h] + mw[n * NTOK + m];
        comb[base + e] = __float2bfloat16(v);
    }
}

// ---------------- LayerNorm (warp per row, bf16 out) -------------------------
template<bool SHIFTMAP>
__global__ void __launch_bounds__(256) ln_kernel(const float* __restrict__ x,
                                                 const float* __restrict__ gw,
                                                 const float* __restrict__ gb,
                                                 bf16* __restrict__ out) {
    int warp = threadIdx.x >> 5, lane = threadIdx.x & 31;
    int m = blockIdx.x * 8 + warp;
    const float* xr;
    if (SHIFTMAP) {
        int r = remap_row(m);
        xr = x + (size_t)r * DIM;
    } else {
        xr = x + (size_t)m * DIM;
    }
    float4 v0 = *(const float4*)(xr + lane * 4);
    float4 v1 = *(const float4*)(xr + 128 + lane * 4);
    float s  = v0.x + v0.y + v0.z + v0.w + v1.x + v1.y + v1.z + v1.w;
    float sq = v0.x*v0.x + v0.y*v0.y + v0.z*v0.z + v0.w*v0.w
             + v1.x*v1.x + v1.y*v1.y + v1.z*v1.z + v1.w*v1.w;
    #pragma unroll
    for (int o = 16; o; o >>= 1) {
        s  += __shfl_xor_sync(0xffffffffu, s,  o);
        sq += __shfl_xor_sync(0xffffffffu, sq, o);
    }
    float mu  = s * (1.0f / DIM);
    float var = sq * (1.0f / DIM) - mu * mu;
    float rs  = rsqrtf(var + 1e-5f);
    float4 w0 = *(const float4*)(gw + lane * 4);
    float4 w1 = *(const float4*)(gw + 128 + lane * 4);
    float4 b0 = *(const float4*)(gb + lane * 4);
    float4 b1 = *(const float4*)(gb + 128 + lane * 4);
    bf16* orow = out + (size_t)m * DIM;
    __nv_bfloat162 p;
    p = {__float2bfloat16((v0.x-mu)*rs*w0.x+b0.x), __float2bfloat16((v0.y-mu)*rs*w0.y+b0.y)};
    *(__nv_bfloat162*)(orow + lane*4)     = p;
    p = {__float2bfloat16((v0.z-mu)*rs*w0.z+b0.z), __float2bfloat16((v0.w-mu)*rs*w0.w+b0.w)};
    *(__nv_bfloat162*)(orow + lane*4 + 2) = p;
    p = {__float2bfloat16((v1.x-mu)*rs*w1.x+b1.x), __float2bfloat16((v1.y-mu)*rs*w1.y+b1.y)};
    *(__nv_bfloat162*)(orow + 128 + lane*4)     = p;
    p = {__float2bfloat16((v1.z-mu)*rs*w1.z+b1.z), __float2bfloat16((v1.w-mu)*rs*w1.w+b1.w)};
    *(__nv_bfloat162*)(orow + 128 + lane*4 + 2) = p;
}

// ============ persistent-B GEMM (256-wide K slice resident in smem) ===========
// 512 threads, warp grid 4(m)x4(n), warp tile 32x64 (R11-proven config).
// lda/ldb = row strides of A and B (elements). K per pass = 256.
// EPI: 0=+bias->bf16   1=+bias,GELU->bf16   2=+bias,remap,+res->f32
//      4=raw->f32      5=f32 +=             6=+accin,+bias,+res->f32 (final)
#define PA_SROW 144
#define PA_STAGE (128 * PA_SROW)        // 18432
#define PB_SROW 528
#define PB_OFF (3 * PA_STAGE)           // 55296
#define PSMEM (PB_OFF + 256 * PB_SROW)  // 190464

template<int EPI>
__global__ void __launch_bounds__(512, 1) pgemm(const bf16* __restrict__ A,
                                               const bf16* __restrict__ Bm,
                                               const float* __restrict__ bias,
                                               void* __restrict__ Cv,
                                               int M, int N, int lda, int ldb,
                                               const float* __restrict__ res,
                                               const float* __restrict__ accin,
                                               int GY) {
    extern __shared__ __align__(16) char smem[];
    uint32_t sbase = smem_u32(smem);
    int tid = threadIdx.x;
    int warp = tid >> 5, lane = tid & 31;
    int bn = blockIdx.x, gy = blockIdx.y;
    int warpM = (warp & 3) * 32;
    int warpN = (warp >> 2) * 64;
    int r = lane >> 2, c = lane & 3;
    int mt = M >> 7;

    uint32_t sB = sbase + PB_OFF;
    // one-time B slice load: 256 rows x 256 cols bf16
    {
        const bf16* Bbase = Bm + (size_t)(bn * 256) * ldb;
        #pragma unroll
        for (int rpt = 0; rpt < 16; rpt++) {
            int ch = tid + rpt * 512;
            int row = ch >> 5, col = ch & 31;
            cp16(sB + row * PB_SROW + col * 16, Bbase + (size_t)row * ldb + col * 8);
        }
    }
    cp_commit();

    uint32_t aoff = (uint32_t)((lane & 15) * PA_SROW + (lane >> 4) * 16);
    uint32_t boff = (uint32_t)(((lane & 7) + ((lane >> 4) << 3)) * PB_SROW
                               + ((lane & 8) ? 16 : 0));

    int ntiles = (mt - gy + GY - 1) / GY;
    int nj = ntiles * 4;

#define FILLA(s, j) do { \
    const bf16* Ab = A + (size_t)(gy + ((j) >> 2) * GY) * 128 * lda + ((j) & 3) * 64; \
    uint32_t as = sbase + (s) * PA_STAGE; \
    _Pragma("unroll") \
    for (int rpt = 0; rpt < 2; rpt++) { \
        int ch = tid + rpt * 512; \
        int row = ch >> 3, col = ch & 7; \
        cp16(as + row * PA_SROW + col * 16, Ab + (size_t)row * lda + col * 8); \
    } \
} while (0)

    FILLA(0, 0);
    cp_commit();
    if (nj > 1) FILLA(1, 1);
    cp_commit();

    for (int t = 0; t < ntiles; t++) {
        int bm = gy + t * GY;
        float acc[2][8][4];
        #pragma unroll
        for (int mi = 0; mi < 2; mi++)
            #pragma unroll
            for (int ni = 0; ni < 8; ni++)
                #pragma unroll
                for (int q = 0; q < 4; q++) acc[mi][ni][q] = 0.0f;

        #pragma unroll
        for (int s4 = 0; s4 < 4; s4++) {
            int j = t * 4 + s4;
            cp_wait<1>();
            __syncthreads();
            if (j + 2 < nj) FILLA((j + 2) % 3, j + 2);
            cp_commit();

            uint32_t As = sbase + (j % 3) * PA_STAGE;
            #pragma unroll
            for (int kk = 0; kk < 4; kk++) {
                int k16 = s4 * 4 + kk;
                uint32_t af[2][4], bfr[4][4];
                #pragma unroll
                for (int mi = 0; mi < 2; mi++)
                    ldsm4(af[mi], As + (uint32_t)((warpM + mi * 16) * PA_SROW + kk * 32) + aoff);
                #pragma unroll
                for (int p = 0; p < 4; p++)
                    ldsm4(bfr[p], sB + (uint32_t)((warpN + p * 16) * PB_SROW + k16 * 32) + boff);
                #pragma unroll
                for (int mi = 0; mi < 2; mi++)
                    #pragma unroll
                    for (int ni = 0; ni < 8; ni++)
                        mma_bf16(acc[mi][ni], af[mi], &bfr[ni >> 1][(ni & 1) * 2]);
            }
        }

        // epilogue
        #pragma unroll
        for (int mi = 0; mi < 2; mi++) {
            #pragma unroll
            for (int half = 0; half < 2; half++) {
                int row = bm * 128 + warpM + mi * 16 + r + half * 8;
                int orow = row;
                if (EPI == 2) orow = remap_row(row);
                const float* rr = (EPI == 2 || EPI == 6) ? res + (size_t)orow * N : nullptr;
                const float* ai = (EPI == 6) ? accin + (size_t)orow * N : nullptr;
                #pragma unroll
                for (int ni = 0; ni < 8; ni++) {
                    int col = bn * 256 + warpN + ni * 8 + 2 * c;
                    float v0 = acc[mi][ni][half * 2 + 0];
                    float v1 = acc[mi][ni][half * 2 + 1];
                    if (EPI == 0 || EPI == 1 || EPI == 2 || EPI == 6) {
                        v0 += bias[col]; v1 += bias[col + 1];
                    }
                    if (EPI == 1) {
                        v0 = 0.5f * v0 * (1.0f + erff(v0 * 0.70710678118654752f));
                        v1 = 0.5f * v1 * (1.0f + erff(v1 * 0.70710678118654752f));
                    }
                    if (EPI == 2) { v0 += rr[col]; v1 += rr[col + 1]; }
                    if (EPI == 6) { v0 += rr[col] + ai[col]; v1 += rr[col + 1] + ai[col + 1]; }
                    if (EPI == 0 || EPI == 1) {
                        bf16* cp = (bf16*)Cv + (size_t)orow * N;
                        __nv_bfloat162 pk = {__float2bfloat16(v0), __float2bfloat16(v1)};
                        *(__nv_bfloat162*)(cp + col) = pk;
                    } else if (EPI == 5) {
                        float* cp = (float*)Cv + (size_t)orow * N;
                        float2 o = *(float2*)(cp + col);
                        o.x += v0; o.y += v1;
                        *(float2*)(cp + col) = o;
                    } else {
                        float* cp = (float*)Cv + (size_t)orow * N;
                        *(float2*)(cp + col) = make_float2(v0, v1);
                    }
                }
            }
        }
    }
#undef FILLA
}

// ---------------- tensor-core windowed attention ------------------------------
__global__ void __launch_bounds__(256) attn_tc(const bf16* __restrict__ qkv,
                                               const bf16* __restrict__ comb,
                                               bf16* __restrict__ out) {
    __shared__ __align__(16) bf16 sQ[2][64 * 40];
    __shared__ __align__(16) bf16 sK[2][64 * 40];
    __shared__ __align__(16) bf16 sVT[2][32 * 72];
    __shared__ __align__(16) bf16 sB[2][64 * 72];

    int tid = threadIdx.x;
    int win = blockIdx.x;
    int hg  = blockIdx.y * 2;
    int w64 = win & 63;

    uint32_t* vz = (uint32_t*)sVT;
    for (int i = tid; i < 2 * 32 * 72 / 2; i += 256) vz[i] = 0;
    for (int i = tid; i < 600; i += 256) {
        int h = i / 300, rm = i % 300;
        int row = 49 + rm / 20, w = rm % 20;
        ((uint32_t*)sQ)[h * 1280 + row * 20 + w] = 0;
        ((uint32_t*)sK)[h * 1280 + row * 20 + w] = 0;
    }
    __syncthreads();

    for (int i = tid; i < 392; i += 256) {
        int h = i / 196, rm = i % 196;
        int tok = rm >> 2, ch = rm & 3;
        const bf16* src = qkv + (size_t)(win * 49 + tok) * 768 + (hg + h) * 32 + ch * 8;
        *(uint4*)((char*)sQ + h * 5120 + tok * 80 + ch * 16) = *(const uint4*)src;
        *(uint4*)((char*)sK + h * 5120 + tok * 80 + ch * 16) = *(const uint4*)(src + 256);
    }
    for (int i = tid; i < 1568; i += 256) {
        int h = i / 784, rm = i % 784;
        int tok = rm / 16, dp = (rm % 16) * 2;
        __nv_bfloat162 v = *(const __nv_bfloat162*)(qkv + (size_t)(win * 49 + tok) * 768
                                                    + 512 + (hg + h) * 32 + dp);
        *(bf16*)((char*)sVT + h * 4608 + dp * 144 + tok * 2)       = v.x;
        *(bf16*)((char*)sVT + h * 4608 + (dp + 1) * 144 + tok * 2) = v.y;
    }
    for (int i = tid; i < 1024; i += 256) {
        int h = i >> 9, rm = i & 511;
        int n = rm >> 3, ch = rm & 7;
        const bf16* src = comb + (((size_t)((w64 * 8 + hg + h) * 64 + n)) << 6) + ch * 8;
        *(uint4*)((char*)sB + h * 9216 + n * 144 + ch * 16) = *(const uint4*)src;
    }
    __syncthreads();

    int warp = tid >> 5, lane = tid & 31;
    int head = warp >> 2;
    int rowbase = (warp & 3) * 16;

    uint32_t Qb = smem_u32(sQ) + head * 5120;
    uint32_t Kb = smem_u32(sK) + head * 5120;
    uint32_t Vb = smem_u32(sVT) + head * 4608;
    uint32_t Bb = smem_u32(sB) + head * 9216;

    uint32_t aoff80  = (uint32_t)((lane & 15) * 80 + (lane >> 4) * 16);
    uint32_t aoff144 = (uint32_t)((lane & 15) * 144 + (lane >> 4) * 16);
    uint32_t boff80  = (uint32_t)(((lane & 7) + ((lane >> 4) << 3)) * 80 + ((lane & 8) ? 16 : 0));
    uint32_t boff144 = (uint32_t)(((lane & 7) + ((lane >> 4) << 3)) * 144 + ((lane & 8) ? 16 : 0));

    float sacc[8][4];
    #pragma unroll
    for (int ni = 0; ni < 8; ni++)
        #pragma unroll
        for (int t = 0; t < 4; t++) sacc[ni][t] = 0.0f;

    #pragma unroll
    for (int ks = 0; ks < 2; ks++) {
        uint32_t aq[4], bk[4][4];
        ldsm4(aq, Qb + (uint32_t)(rowbase * 80 + ks * 32) + aoff80);
        #pragma unroll
        for (int p = 0; p < 4; p++)
            ldsm4(bk[p], Kb + (uint32_t)(p * 16 * 80 + ks * 32) + boff80);
        #pragma unroll
        for (int ni = 0; ni < 8; ni++)
            mma_bf16(sacc[ni], aq, &bk[ni >> 1][(ni & 1) * 2]);
    }

    const float scale = 0.17677669529663687f;
    #pragma unroll
    for (int cg = 0; cg < 4; cg++) {
        uint32_t bb[4];
        ldsm4(bb, Bb + (uint32_t)(rowbase * 144 + cg * 32) + aoff144);
        float2 f;
        f = __bfloat1622float2(*(__nv_bfloat162*)&bb[0]);
        sacc[2*cg][0] = sacc[2*cg][0] * scale + f.x;
        sacc[2*cg][1] = sacc[2*cg][1] * scale + f.y;
        f = __bfloat1622float2(*(__nv_bfloat162*)&bb[1]);
        sacc[2*cg][2] = sacc[2*cg][2] * scale + f.x;
        sacc[2*cg][3] = sacc[2*cg][3] * scale + f.y;
        f = __bfloat1622float2(*(__nv_bfloat162*)&bb[2]);
        sacc[2*cg+1][0] = sacc[2*cg+1][0] * scale + f.x;
        sacc[2*cg+1][1] = sacc[2*cg+1][1] * scale + f.y;
        f = __bfloat1622float2(*(__nv_bfloat162*)&bb[3]);
        sacc[2*cg+1][2] = sacc[2*cg+1][2] * scale + f.x;
        sacc[2*cg+1][3] = sacc[2*cg+1][3] * scale + f.y;
    }

    #pragma unroll
    for (int hf = 0; hf < 2; hf++) {
        int i0 = hf * 2;
        float mx = -1e30f;
        #pragma unroll
        for (int ni = 0; ni < 8; ni++)
            mx = fmaxf(mx, fmaxf(sacc[ni][i0], sacc[ni][i0 + 1]));
        mx = fmaxf(mx, __shfl_xor_sync(0xffffffffu, mx, 1));
        mx = fmaxf(mx, __shfl_xor_sync(0xffffffffu, mx, 2));
        float sum = 0.0f;
        #pragma unroll
        for (int ni = 0; ni < 8; ni++) {
            float e0 = expf(sacc[ni][i0] - mx);
            float e1 = expf(sacc[ni][i0 + 1] - mx);
            sacc[ni][i0] = e0; sacc[ni][i0 + 1] = e1;
            sum += e0 + e1;
        }
        sum += __shfl_xor_sync(0xffffffffu, sum, 1);
        sum += __shfl_xor_sync(0xffffffffu, sum, 2);
        float inv = 1.0f / sum;
        #pragma unroll
        for (int ni = 0; ni < 8; ni++) {
            sacc[ni][i0] *= inv; sacc[ni][i0 + 1] *= inv;
        }
    }

    uint32_t pa[4][4];
    #pragma unroll
    for (int ks = 0; ks < 4; ks++) {
        pa[ks][0] = pack_bf16x2(sacc[2*ks][0],   sacc[2*ks][1]);
        pa[ks][1] = pack_bf16x2(sacc[2*ks][2],   sacc[2*ks][3]);
        pa[ks][2] = pack_bf16x2(sacc[2*ks+1][0], sacc[2*ks+1][1]);
        pa[ks][3] = pack_bf16x2(sacc[2*ks+1][2], sacc[2*ks+1][3]);
    }

    float oacc[4][4];
    #pragma unroll
    for (int ni = 0; ni < 4; ni++)
        #pragma unroll
        for (int t = 0; t < 4; t++) oacc[ni][t] = 0.0f;

    #pragma unroll
    for (int ks = 0; ks < 4; ks++) {
        uint32_t bv[2][4];
        #pragma unroll
        for (int p = 0; p < 2; p++)
            ldsm4(bv[p], Vb + (uint32_t)(p * 16 * 144 + ks * 32) + boff144);
        #pragma unroll
        for (int ni = 0; ni < 4; ni++)
            mma_bf16(oacc[ni], pa[ks], &bv[ni >> 1][(ni & 1) * 2]);
    }

    int gh = hg + head;
    int r0 = rowbase + (lane >> 2);
    #pragma unroll
    for (int ni = 0; ni < 4; ni++) {
        int col = gh * 32 + ni * 8 + (lane & 3) * 2;
        if (r0 < NTOK) {
            __nv_bfloat162 pk = {__float2bfloat16(oacc[ni][0]), __float2bfloat16(oacc[ni][1])};
            *(__nv_bfloat162*)(out + (size_t)(win * 49 + r0) * 256 + col) = pk;
        }
        if (r0 + 8 < NTOK) {
            __nv_bfloat162 pk = {__float2bfloat16(oacc[ni][2]), __float2bfloat16(oacc[ni][3])};
            *(__nv_bfloat162*)(out + (size_t)(win * 49 + r0 + 8) * 256 + col) = pk;
        }
    }
}

// ---------------- launcher ---------------------------------------------------
extern "C" void kernel_launch(void* const* d_in, const int* in_sizes, int n_in,
                              void* d_out, int out_size) {
    const float* x     = (const float*)d_in[0];
    const float* n1w   = (const float*)d_in[1];
    const float* n1b   = (const float*)d_in[2];
    const float* qkvw  = (const float*)d_in[3];
    const float* qkvb  = (const float*)d_in[4];
    const float* rpb   = (const float*)d_in[5];
    const float* projw = (const float*)d_in[6];
    const float* projb = (const float*)d_in[7];
    const float* n2w   = (const float*)d_in[8];
    const float* n2b   = (const float*)d_in[9];
    const float* fc1w  = (const float*)d_in[10];
    const float* fc1b  = (const float*)d_in[11];
    const float* fc2w  = (const float*)d_in[12];
    const float* fc2b  = (const float*)d_in[13];
    const int*   relix = (const int*)d_in[14];
    const float* amask = (const float*)d_in[15];
    float* out = (float*)d_out;

    bf16 *hwin, *qkv, *attn, *h2, *wqkv, *wproj, *wfc1, *wfc2, *comb;
    float *x1, *accb;
    cudaGetSymbolAddress((void**)&hwin, g_hwin);
    cudaGetSymbolAddress((void**)&qkv,  g_qkv);
    cudaGetSymbolAddress((void**)&attn, g_attn);
    cudaGetSymbolAddress((void**)&x1,   g_x1);
    cudaGetSymbolAddress((void**)&h2,   g_h2);
    cudaGetSymbolAddress((void**)&accb, g_acc);
    cudaGetSymbolAddress((void**)&wqkv, g_wqkv);
    cudaGetSymbolAddress((void**)&wproj, g_wproj);
    cudaGetSymbolAddress((void**)&wfc1, g_wfc1);
    cudaGetSymbolAddress((void**)&wfc2, g_wfc2);
    cudaGetSymbolAddress((void**)&comb, g_comb);

    cudaFuncSetAttribute(pgemm<0>, cudaFuncAttributeMaxDynamicSharedMemorySize, PSMEM);
    cudaFuncSetAttribute(pgemm<1>, cudaFuncAttributeMaxDynamicSharedMemorySize, PSMEM);
    cudaFuncSetAttribute(pgemm<2>, cudaFuncAttributeMaxDynamicSharedMemorySize, PSMEM);
    cudaFuncSetAttribute(pgemm<4>, cudaFuncAttributeMaxDynamicSharedMemorySize, PSMEM);
    cudaFuncSetAttribute(pgemm<5>, cudaFuncAttributeMaxDynamicSharedMemorySize, PSMEM);
    cudaFuncSetAttribute(pgemm<6>, cudaFuncAttributeMaxDynamicSharedMemorySize, PSMEM);

    cvt4_kernel<<<dim3(DIM * HIDDEN / 4 / 256, 4), 256>>>(
        qkvw, wqkv, 3 * DIM * DIM,
        projw, wproj, DIM * DIM,
        fc1w, wfc1, HIDDEN * DIM,
        fc2w, wfc2, DIM * HIDDEN);
    comb_kernel<<<dim3(64, 8), 256>>>(rpb, relix, amask, comb);

    // 1. LN1 + shift + window-partition (bf16 out)
    ln_kernel<true><<<MTOT / 8, 256>>>(x, n1w, n1b, hwin);
    // 2. QKV GEMM (persistent-B) -> bf16
    pgemm<0><<<dim3(3, 49), 512, PSMEM>>>(hwin, wqkv, qkvb, qkv, MTOT, 3 * DIM,
                                          DIM, DIM, nullptr, nullptr, 49);
    // 3. tensor-core windowed attention
    attn_tc<<<dim3(BZ * NWIN, 4), 256>>>(qkv, comb, attn);
    // 4. proj GEMM (persistent-B) + window-reverse scatter + residual -> f32
    pgemm<2><<<dim3(1, 148), 512, PSMEM>>>(attn, wproj, projb, x1, MTOT, DIM,
                                           DIM, DIM, x, nullptr, 148);
    // 5. LN2 (bf16 out)
    ln_kernel<false><<<MTOT / 8, 256>>>(x1, n2w, n2b, hwin);
    // 6. FC1 + GELU (persistent-B) -> bf16
    pgemm<1><<<dim3(4, 37), 512, PSMEM>>>(hwin, wfc1, fc1b, h2, MTOT, HIDDEN,
                                          DIM, DIM, nullptr, nullptr, 37);
    // 7. FC2 split-K (4 persistent passes, K=256 each)
    pgemm<4><<<dim3(1, 148), 512, PSMEM>>>(h2,       wfc2,       fc2b, accb,
                                           MTOT, DIM, HIDDEN, HIDDEN,
                                           nullptr, nullptr, 148);
    pgemm<5><<<dim3(1, 148), 512, PSMEM>>>(h2 + 256, wfc2 + 256, fc2b, accb,
                                           MTOT, DIM, HIDDEN, HIDDEN,
                                           nullptr, nullptr, 148);
    pgemm<5><<<dim3(1, 148), 512, PSMEM>>>(h2 + 512, wfc2 + 512, fc2b, accb,
                                           MTOT, DIM, HIDDEN, HIDDEN,
                                           nullptr, nullptr, 148);
    pgemm<6><<<dim3(1, 148), 512, PSMEM>>>(h2 + 768, wfc2 + 768, fc2b, out,
                                           MTOT, DIM, HIDDEN, HIDDEN,
                                           x1, accb, 148);
}

// round 14
// speedup vs baseline: 1.4940x; 1.2736x over previous
#include <cuda_runtime.h>
#include <cuda_bf16.h>
#include <math.h>
#include <stdint.h>

#define BZ 32
#define HH 56
#define WW 56
#define DIM 256
#define HEADS 8
#define WS 7
#define SHIFT 3
#define NTOK 49
#define NWIN 64
#define HEAD_DIM 32
#define HIDDEN 1024
#define MTOT (BZ*HH*WW)    // 100352 rows

typedef __nv_bfloat16 bf16;

// ---------------- scratch ----------------------------------------------------
__device__ bf16  g_hwin[(size_t)MTOT * DIM];
__device__ bf16  g_qkv [(size_t)MTOT * 3 * DIM];
__device__ bf16  g_attn[(size_t)MTOT * DIM];
__device__ float g_x1  [(size_t)MTOT * DIM];
__device__ bf16  g_h2  [(size_t)MTOT * HIDDEN];
__device__ bf16  g_wqkv[3 * DIM * DIM];
__device__ bf16  g_wproj[DIM * DIM];
__device__ bf16  g_wfc1[HIDDEN * DIM];
__device__ bf16  g_wfc2[DIM * HIDDEN];
__device__ bf16  g_comb[64 * 8 * 64 * 64];

__device__ __forceinline__ int remap_row(int m) {
    int b    = m / (NWIN * NTOK);
    int rem  = m - b * (NWIN * NTOK);
    int wimg = rem / NTOK;
    int n    = rem - wimg * NTOK;
    int hh = (wimg >> 3) * WS + n / WS + SHIFT; if (hh >= HH) hh -= HH;
    int ww = (wimg & 7) * WS + n % WS + SHIFT;  if (ww >= WW) ww -= WW;
    return b * (HH * WW) + hh * WW + ww;
}

// ---------------- ptx helpers -------------------------------------------------
__device__ __forceinline__ uint32_t smem_u32(const void* p) {
    return (uint32_t)__cvta_generic_to_shared(p);
}
__device__ __forceinline__ void cp16(uint32_t dst, const void* src) {
    asm volatile("cp.async.cg.shared.global [%0], [%1], 16;\n" :: "r"(dst), "l"(src));
}
__device__ __forceinline__ void cp_commit() { asm volatile("cp.async.commit_group;\n"); }
template<int N> __device__ __forceinline__ void cp_wait() {
    asm volatile("cp.async.wait_group %0;\n" :: "n"(N));
}
__device__ __forceinline__ void mbar_init(uint32_t a, uint32_t cnt) {
    asm volatile("mbarrier.init.shared.b64 [%0], %1;" :: "r"(a), "r"(cnt) : "memory");
}
__device__ __forceinline__ void mbar_expect(uint32_t a, uint32_t bytes) {
    asm volatile("mbarrier.arrive.expect_tx.shared.b64 _, [%0], %1;"
                 :: "r"(a), "r"(bytes) : "memory");
}
__device__ __forceinline__ void mbar_wait(uint32_t a, uint32_t parity) {
    asm volatile("{\n\t.reg .pred P;\n"
                 "LAB%=:\n\tmbarrier.try_wait.parity.acquire.cta.shared::cta.b64 P, [%0], %1;\n"
                 "\t@!P bra LAB%=;\n\t}"
                 :: "r"(a), "r"(parity) : "memory");
}
__device__ __forceinline__ void cpbulk(uint32_t dst, const void* src, uint32_t bytes,
                                       uint32_t mbar) {
    asm volatile("cp.async.bulk.shared::cluster.global.mbarrier::complete_tx::bytes "
                 "[%0], [%1], %2, [%3];"
                 :: "r"(dst), "l"(src), "r"(bytes), "r"(mbar) : "memory");
}
__device__ __forceinline__ void ldsm4(uint32_t* r, uint32_t addr) {
    asm volatile("ldmatrix.sync.aligned.m8n8.x4.shared.b16 {%0,%1,%2,%3}, [%4];"
                 : "=r"(r[0]), "=r"(r[1]), "=r"(r[2]), "=r"(r[3]) : "r"(addr));
}
__device__ __forceinline__ void mma_bf16(float* d, const uint32_t* a, const uint32_t* b) {
    asm volatile(
        "mma.sync.aligned.m16n8k16.row.col.f32.bf16.bf16.f32 "
        "{%0,%1,%2,%3}, {%4,%5,%6,%7}, {%8,%9}, {%0,%1,%2,%3};\n"
        : "+f"(d[0]), "+f"(d[1]), "+f"(d[2]), "+f"(d[3])
        : "r"(a[0]), "r"(a[1]), "r"(a[2]), "r"(a[3]), "r"(b[0]), "r"(b[1]));
}
__device__ __forceinline__ uint32_t pack_bf16x2(float a, float b) {
    __nv_bfloat162 h;
    h.x = __float2bfloat16(a); h.y = __float2bfloat16(b);
    return *(uint32_t*)&h;
}

// ---------------- fp32 -> bf16 weight convert (fused, 4 segs) -----------------
__global__ void cvt4_kernel(const float* s0, bf16* d0, int n0,
                            const float* s1, bf16* d1, int n1,
                            const float* s2, bf16* d2, int n2,
                            const float* s3, bf16* d3, int n3) {
    const float* s; bf16* d; int n;
    switch (blockIdx.y) {
        case 0: s = s0; d = d0; n = n0; break;
        case 1: s = s1; d = d1; n = n1; break;
        case 2: s = s2; d = d2; n = n2; break;
        default: s = s3; d = d3; n = n3; break;
    }
    int i = (blockIdx.x * blockDim.x + threadIdx.x) * 4;
    if (i < n) {
        float4 v = *(const float4*)(s + i);
        __nv_bfloat162 p0 = {__float2bfloat16(v.x), __float2bfloat16(v.y)};
        __nv_bfloat162 p1 = {__float2bfloat16(v.z), __float2bfloat16(v.w)};
        *(__nv_bfloat162*)(d + i)     = p0;
        *(__nv_bfloat162*)(d + i + 2) = p1;
    }
}

// ---------------- comb bias precompute ---------------------------------------
__global__ void comb_kernel(const float* __restrict__ rpb,
                            const int* __restrict__ relix,
                            const float* __restrict__ mask,
                            bf16* __restrict__ comb) {
    int w = blockIdx.x, h = blockIdx.y;
    const float* mw = mask + w * (NTOK * NTOK);
    size_t base = ((size_t)(w * 8 + h)) << 12;
    for (int e = threadIdx.x; e < 4096; e += 256) {
        int n = e >> 6, m = e & 63;
        float v = -1e30f;
        if (n < NTOK && m < NTOK)
            v = rpb[relix[n * NTOK + m] * HEADS + h] + mw[n * NTOK + m];
        comb[base + e] = __float2bfloat16(v);
    }
}

// ---------------- LayerNorm (warp per row, bf16 out) -------------------------
template<bool SHIFTMAP>
__global__ void __launch_bounds__(256) ln_kernel(const float* __restrict__ x,
                                                 const float* __restrict__ gw,
                                                 const float* __restrict__ gb,
                                                 bf16* __restrict__ out) {
    int warp = threadIdx.x >> 5, lane = threadIdx.x & 31;
    int m = blockIdx.x * 8 + warp;
    const float* xr;
    if (SHIFTMAP) {
        int r = remap_row(m);
        xr = x + (size_t)r * DIM;
    } else {
        xr = x + (size_t)m * DIM;
    }
    float4 v0 = *(const float4*)(xr + lane * 4);
    float4 v1 = *(const float4*)(xr + 128 + lane * 4);
    float s  = v0.x + v0.y + v0.z + v0.w + v1.x + v1.y + v1.z + v1.w;
    float sq = v0.x*v0.x + v0.y*v0.y + v0.z*v0.z + v0.w*v0.w
             + v1.x*v1.x + v1.y*v1.y + v1.z*v1.z + v1.w*v1.w;
    #pragma unroll
    for (int o = 16; o; o >>= 1) {
        s  += __shfl_xor_sync(0xffffffffu, s,  o);
        sq += __shfl_xor_sync(0xffffffffu, sq, o);
    }
    float mu  = s * (1.0f / DIM);
    float var = sq * (1.0f / DIM) - mu * mu;
    float rs  = rsqrtf(var + 1e-5f);
    float4 w0 = *(const float4*)(gw + lane * 4);
    float4 w1 = *(const float4*)(gw + 128 + lane * 4);
    float4 b0 = *(const float4*)(gb + lane * 4);
    float4 b1 = *(const float4*)(gb + 128 + lane * 4);
    bf16* orow = out + (size_t)m * DIM;
    __nv_bfloat162 p;
    p = {__float2bfloat16((v0.x-mu)*rs*w0.x+b0.x), __float2bfloat16((v0.y-mu)*rs*w0.y+b0.y)};
    *(__nv_bfloat162*)(orow + lane*4)     = p;
    p = {__float2bfloat16((v0.z-mu)*rs*w0.z+b0.z), __float2bfloat16((v0.w-mu)*rs*w0.w+b0.w)};
    *(__nv_bfloat162*)(orow + lane*4 + 2) = p;
    p = {__float2bfloat16((v1.x-mu)*rs*w1.x+b1.x), __float2bfloat16((v1.y-mu)*rs*w1.y+b1.y)};
    *(__nv_bfloat162*)(orow + 128 + lane*4)     = p;
    p = {__float2bfloat16((v1.z-mu)*rs*w1.z+b1.z), __float2bfloat16((v1.w-mu)*rs*w1.w+b1.w)};
    *(__nv_bfloat162*)(orow + 128 + lane*4 + 2) = p;
}

// ============ persistent-B GEMM (K=256), bulk-copy A stream ===================
// 512 threads, warp grid 4(m)x4(n), warp tile 32x64 (R11 config).
// smem: [0..24) 3 mbarriers; [64..) A ring 3 x 18432; then B 256 x 528.
#define PMB 0
#define PA_OFF 64
#define PA_SROW 144
#define PA_STAGE (128 * PA_SROW)
#define PB_SROW 528
#define PB_OFF (PA_OFF + 3 * PA_STAGE)      // 55360
#define PSMEM (PB_OFF + 256 * PB_SROW)      // 190528

template<int EPI>
__global__ void __launch_bounds__(512, 1) pgemm(const bf16* __restrict__ A,
                                               const bf16* __restrict__ Bm,
                                               const float* __restrict__ bias,
                                               void* __restrict__ Cv,
                                               int M, int N, int lda, int ldb,
                                               const float* __restrict__ res,
                                               int GY) {
    extern __shared__ __align__(128) char smem[];
    uint32_t sbase = smem_u32(smem);
    int tid = threadIdx.x;
    int warp = tid >> 5, lane = tid & 31;
    int bn = blockIdx.x, gy = blockIdx.y;
    int warpM = (warp & 3) * 32;
    int warpN = (warp >> 2) * 64;
    int r = lane >> 2, c = lane & 3;
    int mt = M >> 7;

    if (tid == 0) {
        mbar_init(sbase + PMB + 0, 128);
        mbar_init(sbase + PMB + 8, 128);
        mbar_init(sbase + PMB + 16, 128);
    }
    uint32_t sB = sbase + PB_OFF;
    // one-time B slice (256x256 bf16) via cp.async
    {
        const bf16* Bbase = Bm + (size_t)(bn * 256) * ldb;
        #pragma unroll
        for (int rpt = 0; rpt < 16; rpt++) {
            int ch = tid + rpt * 512;
            int row = ch >> 5, col = ch & 31;
            cp16(sB + row * PB_SROW + col * 16, Bbase + (size_t)row * ldb + col * 8);
        }
    }
    cp_commit();
    __syncthreads();   // mbarrier init visible before first bulk

    uint32_t aoff = (uint32_t)((lane & 15) * PA_SROW + (lane >> 4) * 16);
    uint32_t boff = (uint32_t)(((lane & 7) + ((lane >> 4) << 3)) * PB_SROW
                               + ((lane & 8) ? 16 : 0));

    int ntiles = (mt - gy + GY - 1) / GY;
    int nj = ntiles * 4;

#define FILLA(s, j) do { \
    if (tid < 128) { \
        const bf16* Ab = A + (size_t)(gy + ((j) >> 2) * GY) * 128 * lda \
                         + ((j) & 3) * 64 + (size_t)tid * lda; \
        uint32_t mb = sbase + PMB + (s) * 8; \
        mbar_expect(mb, 128); \
        cpbulk(sbase + PA_OFF + (s) * PA_STAGE + tid * PA_SROW, Ab, 128, mb); \
    } \
} while (0)

    FILLA(0, 0);
    if (nj > 1) FILLA(1, 1);
    cp_wait<0>();      // B resident (per-thread); ordered w.r.t. all via loop syncthreads

    for (int t = 0; t < ntiles; t++) {
        int bm = gy + t * GY;
        float acc[2][8][4];
        #pragma unroll
        for (int mi = 0; mi < 2; mi++)
            #pragma unroll
            for (int ni = 0; ni < 8; ni++)
                #pragma unroll
                for (int q = 0; q < 4; q++) acc[mi][ni][q] = 0.0f;

        #pragma unroll
        for (int s4 = 0; s4 < 4; s4++) {
            int j = t * 4 + s4;
            int st = j % 3;
            mbar_wait(sbase + PMB + st * 8, (uint32_t)((j / 3) & 1));
            __syncthreads();
            if (j + 2 < nj) FILLA((j + 2) % 3, j + 2);

            uint32_t As = sbase + PA_OFF + st * PA_STAGE;
            #pragma unroll
            for (int kk = 0; kk < 4; kk++) {
                int k16 = s4 * 4 + kk;
                uint32_t af[2][4], bfr[4][4];
                #pragma unroll
                for (int mi = 0; mi < 2; mi++)
                    ldsm4(af[mi], As + (uint32_t)((warpM + mi * 16) * PA_SROW + kk * 32) + aoff);
                #pragma unroll
                for (int p = 0; p < 4; p++)
                    ldsm4(bfr[p], sB + (uint32_t)((warpN + p * 16) * PB_SROW + k16 * 32) + boff);
                #pragma unroll
                for (int mi = 0; mi < 2; mi++)
                    #pragma unroll
                    for (int ni = 0; ni < 8; ni++)
                        mma_bf16(acc[mi][ni], af[mi], &bfr[ni >> 1][(ni & 1) * 2]);
            }
        }

        // epilogue
        #pragma unroll
        for (int mi = 0; mi < 2; mi++) {
            #pragma unroll
            for (int half = 0; half < 2; half++) {
                int row = bm * 128 + warpM + mi * 16 + r + half * 8;
                int orow = row;
                if (EPI == 2) orow = remap_row(row);
                const float* rr = (EPI == 2) ? res + (size_t)orow * N : nullptr;
                #pragma unroll
                for (int ni = 0; ni < 8; ni++) {
                    int col = bn * 256 + warpN + ni * 8 + 2 * c;
                    float v0 = acc[mi][ni][half * 2 + 0] + bias[col];
                    float v1 = acc[mi][ni][half * 2 + 1] + bias[col + 1];
                    if (EPI == 1) {
                        v0 = 0.5f * v0 * (1.0f + erff(v0 * 0.70710678118654752f));
                        v1 = 0.5f * v1 * (1.0f + erff(v1 * 0.70710678118654752f));
                    }
                    if (EPI == 2) { v0 += rr[col]; v1 += rr[col + 1]; }
                    if (EPI == 0 || EPI == 1) {
                        bf16* cp = (bf16*)Cv + (size_t)orow * N;
                        __nv_bfloat162 pk = {__float2bfloat16(v0), __float2bfloat16(v1)};
                        *(__nv_bfloat162*)(cp + col) = pk;
                    } else {
                        float* cp = (float*)Cv + (size_t)orow * N;
                        *(float2*)(cp + col) = make_float2(v0, v1);
                    }
                }
            }
        }
    }
#undef FILLA
}

// ---------------- streaming GEMM (fc2, K=1024), bulk-copy A+B ----------------
#define SMB 0
#define S_OFF 64
#define SROW 144
#define ASTAGE (128 * SROW)
#define BSTAGE (256 * SROW)
#define STAGEB (ASTAGE + BSTAGE)           // 55296
#define SMEM_DYN (S_OFF + 3 * STAGEB)      // 165952

template<int EPI>
__global__ void __launch_bounds__(512, 1) bgemm(const bf16* __restrict__ A,
                                               const bf16* __restrict__ Bm,
                                               const float* __restrict__ bias,
                                               void* __restrict__ Cv,
                                               int M, int N, int K,
                                               const float* __restrict__ res) {
    extern __shared__ __align__(128) char smem[];
    uint32_t sbase = smem_u32(smem);
    int tid = threadIdx.x;
    int bn = blockIdx.x, bm = blockIdx.y;
    int warp = tid >> 5, lane = tid & 31;
    int warpM = (warp & 3) * 32;
    int warpN = (warp >> 2) * 64;
    int r = lane >> 2, c = lane & 3;

    if (tid == 0) {
        mbar_init(sbase + SMB + 0, 384);
        mbar_init(sbase + SMB + 8, 384);
        mbar_init(sbase + SMB + 16, 384);
    }
    __syncthreads();

    const bf16* Abase = A  + (size_t)(bm * 128) * K;
    const bf16* Bbase = Bm + (size_t)(bn * 256) * K;

    uint32_t aoff = (uint32_t)((lane & 15) * SROW + (lane >> 4) * 16);
    uint32_t boff = (uint32_t)(((lane & 7) + ((lane >> 4) << 3)) * SROW + ((lane & 8) ? 16 : 0));

    float acc[2][8][4];
    #pragma unroll
    for (int mi = 0; mi < 2; mi++)
        #pragma unroll
        for (int ni = 0; ni < 8; ni++)
            #pragma unroll
            for (int t = 0; t < 4; t++) acc[mi][ni][t] = 0.0f;

#define FILL(s, k0) do { \
    uint32_t mb = sbase + SMB + (s) * 8; \
    uint32_t ab = sbase + S_OFF + (s) * STAGEB; \
    if (tid < 128) { \
        mbar_expect(mb, 128); \
        cpbulk(ab + tid * SROW, Abase + (size_t)tid * K + (k0), 128, mb); \
    } else if (tid < 384) { \
        int row = tid - 128; \
        mbar_expect(mb, 128); \
        cpbulk(ab + ASTAGE + row * SROW, Bbase + (size_t)row * K + (k0), 128, mb); \
    } \
} while (0)

    int nk = K >> 6;
    FILL(0, 0);
    FILL(1, 64);

    for (int i = 0; i < nk; i++) {
        int st = i % 3;
        mbar_wait(sbase + SMB + st * 8, (uint32_t)((i / 3) & 1));
        __syncthreads();
        if (i + 2 < nk) FILL((i + 2) % 3, (i + 2) * 64);

        uint32_t Ab = sbase + S_OFF + st * STAGEB;
        uint32_t Bb = Ab + ASTAGE;
        #pragma unroll
        for (int kk = 0; kk < 4; kk++) {
            uint32_t af[2][4], bfr[4][4];
            #pragma unroll
            for (int mi = 0; mi < 2; mi++)
                ldsm4(af[mi], Ab + (uint32_t)((warpM + mi * 16) * SROW + kk * 32) + aoff);
            #pragma unroll
            for (int p = 0; p < 4; p++)
                ldsm4(bfr[p], Bb + (uint32_t)((warpN + p * 16) * SROW + kk * 32) + boff);
            #pragma unroll
            for (int mi = 0; mi < 2; mi++)
                #pragma unroll
                for (int ni = 0; ni < 8; ni++)
                    mma_bf16(acc[mi][ni], af[mi], &bfr[ni >> 1][(ni & 1) * 2]);
        }
    }

    #pragma unroll
    for (int mi = 0; mi < 2; mi++) {
        #pragma unroll
        for (int half = 0; half < 2; half++) {
            int row = bm * 128 + warpM + mi * 16 + r + half * 8;
            const float* rr = res + (size_t)row * N;
            #pragma unroll
            for (int ni = 0; ni < 8; ni++) {
                int col = bn * 256 + warpN + ni * 8 + 2 * c;
                float v0 = acc[mi][ni][half * 2 + 0] + bias[col] + rr[col];
                float v1 = acc[mi][ni][half * 2 + 1] + bias[col + 1] + rr[col + 1];
                float* cp = (float*)Cv + (size_t)row * N;
                *(float2*)(cp + col) = make_float2(v0, v1);
            }
        }
    }
#undef FILL
}

// ---------------- tensor-core windowed attention ------------------------------
__global__ void __launch_bounds__(256) attn_tc(const bf16* __restrict__ qkv,
                                               const bf16* __restrict__ comb,
                                               bf16* __restrict__ out) {
    __shared__ __align__(16) bf16 sQ[2][64 * 40];
    __shared__ __align__(16) bf16 sK[2][64 * 40];
    __shared__ __align__(16) bf16 sVT[2][32 * 72];
    __shared__ __align__(16) bf16 sB[2][64 * 72];

    int tid = threadIdx.x;
    int win = blockIdx.x;
    int hg  = blockIdx.y * 2;
    int w64 = win & 63;

    uint32_t* vz = (uint32_t*)sVT;
    for (int i = tid; i < 2 * 32 * 72 / 2; i += 256) vz[i] = 0;
    for (int i = tid; i < 600; i += 256) {
        int h = i / 300, rm = i % 300;
        int row = 49 + rm / 20, w = rm % 20;
        ((uint32_t*)sQ)[h * 1280 + row * 20 + w] = 0;
        ((uint32_t*)sK)[h * 1280 + row * 20 + w] = 0;
    }
    __syncthreads();

    for (int i = tid; i < 392; i += 256) {
        int h = i / 196, rm = i % 196;
        int tok = rm >> 2, ch = rm & 3;
        const bf16* src = qkv + (size_t)(win * 49 + tok) * 768 + (hg + h) * 32 + ch * 8;
        *(uint4*)((char*)sQ + h * 5120 + tok * 80 + ch * 16) = *(const uint4*)src;
        *(uint4*)((char*)sK + h * 5120 + tok * 80 + ch * 16) = *(const uint4*)(src + 256);
    }
    for (int i = tid; i < 1568; i += 256) {
        int h = i / 784, rm = i % 784;
        int tok = rm / 16, dp = (rm % 16) * 2;
        __nv_bfloat162 v = *(const __nv_bfloat162*)(qkv + (size_t)(win * 49 + tok) * 768
                                                    + 512 + (hg + h) * 32 + dp);
        *(bf16*)((char*)sVT + h * 4608 + dp * 144 + tok * 2)       = v.x;
        *(bf16*)((char*)sVT + h * 4608 + (dp + 1) * 144 + tok * 2) = v.y;
    }
    for (int i = tid; i < 1024; i += 256) {
        int h = i >> 9, rm = i & 511;
        int n = rm >> 3, ch = rm & 7;
        const bf16* src = comb + (((size_t)((w64 * 8 + hg + h) * 64 + n)) << 6) + ch * 8;
        *(uint4*)((char*)sB + h * 9216 + n * 144 + ch * 16) = *(const uint4*)src;
    }
    __syncthreads();

    int warp = tid >> 5, lane = tid & 31;
    int head = warp >> 2;
    int rowbase = (warp & 3) * 16;

    uint32_t Qb = smem_u32(sQ) + head * 5120;
    uint32_t Kb = smem_u32(sK) + head * 5120;
    uint32_t Vb = smem_u32(sVT) + head * 4608;
    uint32_t Bb = smem_u32(sB) + head * 9216;

    uint32_t aoff80  = (uint32_t)((lane & 15) * 80 + (lane >> 4) * 16);
    uint32_t aoff144 = (uint32_t)((lane & 15) * 144 + (lane >> 4) * 16);
    uint32_t boff80  = (uint32_t)(((lane & 7) + ((lane >> 4) << 3)) * 80 + ((lane & 8) ? 16 : 0));
    uint32_t boff144 = (uint32_t)(((lane & 7) + ((lane >> 4) << 3)) * 144 + ((lane & 8) ? 16 : 0));

    float sacc[8][4];
    #pragma unroll
    for (int ni = 0; ni < 8; ni++)
        #pragma unroll
        for (int t = 0; t < 4; t++) sacc[ni][t] = 0.0f;

    #pragma unroll
    for (int ks = 0; ks < 2; ks++) {
        uint32_t aq[4], bk[4][4];
        ldsm4(aq, Qb + (uint32_t)(rowbase * 80 + ks * 32) + aoff80);
        #pragma unroll
        for (int p = 0; p < 4; p++)
            ldsm4(bk[p], Kb + (uint32_t)(p * 16 * 80 + ks * 32) + boff80);
        #pragma unroll
        for (int ni = 0; ni < 8; ni++)
            mma_bf16(sacc[ni], aq, &bk[ni >> 1][(ni & 1) * 2]);
    }

    const float scale = 0.17677669529663687f;
    #pragma unroll
    for (int cg = 0; cg < 4; cg++) {
        uint32_t bb[4];
        ldsm4(bb, Bb + (uint32_t)(rowbase * 144 + cg * 32) + aoff144);
        float2 f;
        f = __bfloat1622float2(*(__nv_bfloat162*)&bb[0]);
        sacc[2*cg][0] = sacc[2*cg][0] * scale + f.x;
        sacc[2*cg][1] = sacc[2*cg][1] * scale + f.y;
        f = __bfloat1622float2(*(__nv_bfloat162*)&bb[1]);
        sacc[2*cg][2] = sacc[2*cg][2] * scale + f.x;
        sacc[2*cg][3] = sacc[2*cg][3] * scale + f.y;
        f = __bfloat1622float2(*(__nv_bfloat162*)&bb[2]);
        sacc[2*cg+1][0] = sacc[2*cg+1][0] * scale + f.x;
        sacc[2*cg+1][1] = sacc[2*cg+1][1] * scale + f.y;
        f = __bfloat1622float2(*(__nv_bfloat162*)&bb[3]);
        sacc[2*cg+1][2] = sacc[2*cg+1][2] * scale + f.x;
        sacc[2*cg+1][3] = sacc[2*cg+1][3] * scale + f.y;
    }

    #pragma unroll
    for (int hf = 0; hf < 2; hf++) {
        int i0 = hf * 2;
        float mx = -1e30f;
        #pragma unroll
        for (int ni = 0; ni < 8; ni++)
            mx = fmaxf(mx, fmaxf(sacc[ni][i0], sacc[ni][i0 + 1]));
        mx = fmaxf(mx, __shfl_xor_sync(0xffffffffu, mx, 1));
        mx = fmaxf(mx, __shfl_xor_sync(0xffffffffu, mx, 2));
        float sum = 0.0f;
        #pragma unroll
        for (int ni = 0; ni < 8; ni++) {
            float e0 = expf(sacc[ni][i0] - mx);
            float e1 = expf(sacc[ni][i0 + 1] - mx);
            sacc[ni][i0] = e0; sacc[ni][i0 + 1] = e1;
            sum += e0 + e1;
        }
        sum += __shfl_xor_sync(0xffffffffu, sum, 1);
        sum += __shfl_xor_sync(0xffffffffu, sum, 2);
        float inv = 1.0f / sum;
        #pragma unroll
        for (int ni = 0; ni < 8; ni++) {
            sacc[ni][i0] *= inv; sacc[ni][i0 + 1] *= inv;
        }
    }

    uint32_t pa[4][4];
    #pragma unroll
    for (int ks = 0; ks < 4; ks++) {
        pa[ks][0] = pack_bf16x2(sacc[2*ks][0],   sacc[2*ks][1]);
        pa[ks][1] = pack_bf16x2(sacc[2*ks][2],   sacc[2*ks][3]);
        pa[ks][2] = pack_bf16x2(sacc[2*ks+1][0], sacc[2*ks+1][1]);
        pa[ks][3] = pack_bf16x2(sacc[2*ks+1][2], sacc[2*ks+1][3]);
    }

    float oacc[4][4];
    #pragma unroll
    for (int ni = 0; ni < 4; ni++)
        #pragma unroll
        for (int t = 0; t < 4; t++) oacc[ni][t] = 0.0f;

    #pragma unroll
    for (int ks = 0; ks < 4; ks++) {
        uint32_t bv[2][4];
        #pragma unroll
        for (int p = 0; p < 2; p++)
            ldsm4(bv[p], Vb + (uint32_t)(p * 16 * 144 + ks * 32) + boff144);
        #pragma unroll
        for (int ni = 0; ni < 4; ni++)
            mma_bf16(oacc[ni], pa[ks], &bv[ni >> 1][(ni & 1) * 2]);
    }

    int gh = hg + head;
    int r0 = rowbase + (lane >> 2);
    #pragma unroll
    for (int ni = 0; ni < 4; ni++) {
        int col = gh * 32 + ni * 8 + (lane & 3) * 2;
        if (r0 < NTOK) {
            __nv_bfloat162 pk = {__float2bfloat16(oacc[ni][0]), __float2bfloat16(oacc[ni][1])};
            *(__nv_bfloat162*)(out + (size_t)(win * 49 + r0) * 256 + col) = pk;
        }
        if (r0 + 8 < NTOK) {
            __nv_bfloat162 pk = {__float2bfloat16(oacc[ni][2]), __float2bfloat16(oacc[ni][3])};
            *(__nv_bfloat162*)(out + (size_t)(win * 49 + r0 + 8) * 256 + col) = pk;
        }
    }
}

// ---------------- launcher ---------------------------------------------------
extern "C" void kernel_launch(void* const* d_in, const int* in_sizes, int n_in,
                              void* d_out, int out_size) {
    const float* x     = (const float*)d_in[0];
    const float* n1w   = (const float*)d_in[1];
    const float* n1b   = (const float*)d_in[2];
    const float* qkvw  = (const float*)d_in[3];
    const float* qkvb  = (const float*)d_in[4];
    const float* rpb   = (const float*)d_in[5];
    const float* projw = (const float*)d_in[6];
    const float* projb = (const float*)d_in[7];
    const float* n2w   = (const float*)d_in[8];
    const float* n2b   = (const float*)d_in[9];
    const float* fc1w  = (const float*)d_in[10];
    const float* fc1b  = (const float*)d_in[11];
    const float* fc2w  = (const float*)d_in[12];
    const float* fc2b  = (const float*)d_in[13];
    const int*   relix = (const int*)d_in[14];
    const float* amask = (const float*)d_in[15];
    float* out = (float*)d_out;

    bf16 *hwin, *qkv, *attn, *h2, *wqkv, *wproj, *wfc1, *wfc2, *comb;
    float *x1;
    cudaGetSymbolAddress((void**)&hwin, g_hwin);
    cudaGetSymbolAddress((void**)&qkv,  g_qkv);
    cudaGetSymbolAddress((void**)&attn, g_attn);
    cudaGetSymbolAddress((void**)&x1,   g_x1);
    cudaGetSymbolAddress((void**)&h2,   g_h2);
    cudaGetSymbolAddress((void**)&wqkv, g_wqkv);
    cudaGetSymbolAddress((void**)&wproj, g_wproj);
    cudaGetSymbolAddress((void**)&wfc1, g_wfc1);
    cudaGetSymbolAddress((void**)&wfc2, g_wfc2);
    cudaGetSymbolAddress((void**)&comb, g_comb);

    cudaFuncSetAttribute(pgemm<0>, cudaFuncAttributeMaxDynamicSharedMemorySize, PSMEM);
    cudaFuncSetAttribute(pgemm<1>, cudaFuncAttributeMaxDynamicSharedMemorySize, PSMEM);
    cudaFuncSetAttribute(pgemm<2>, cudaFuncAttributeMaxDynamicSharedMemorySize, PSMEM);
    cudaFuncSetAttribute(bgemm<3>, cudaFuncAttributeMaxDynamicSharedMemorySize, SMEM_DYN);

    cvt4_kernel<<<dim3(DIM * HIDDEN / 4 / 256, 4), 256>>>(
        qkvw, wqkv, 3 * DIM * DIM,
        projw, wproj, DIM * DIM,
        fc1w, wfc1, HIDDEN * DIM,
        fc2w, wfc2, DIM * HIDDEN);
    comb_kernel<<<dim3(64, 8), 256>>>(rpb, relix, amask, comb);

    // 1. LN1 + shift + window-partition (bf16 out)
    ln_kernel<true><<<MTOT / 8, 256>>>(x, n1w, n1b, hwin);
    // 2. QKV GEMM (persistent-B, bulk A) -> bf16
    pgemm<0><<<dim3(3, 49), 512, PSMEM>>>(hwin, wqkv, qkvb, qkv, MTOT, 3 * DIM,
                                          DIM, DIM, nullptr, 49);
    // 3. tensor-core windowed attention
    attn_tc<<<dim3(BZ * NWIN, 4), 256>>>(qkv, comb, attn);
    // 4. proj GEMM (persistent-B) + window-reverse scatter + residual -> f32
    pgemm<2><<<dim3(1, 148), 512, PSMEM>>>(attn, wproj, projb, x1, MTOT, DIM,
                                           DIM, DIM, x, 148);
    // 5. LN2 (bf16 out)
    ln_kernel<false><<<MTOT / 8, 256>>>(x1, n2w, n2b, hwin);
    // 6. FC1 + GELU (persistent-B) -> bf16
    pgemm<1><<<dim3(4, 37), 512, PSMEM>>>(hwin, wfc1, fc1b, h2, MTOT, HIDDEN,
                                          DIM, DIM, nullptr, 37);
    // 7. FC2 + residual -> out (f32) (streaming, bulk A+B)
    bgemm<3><<<dim3(1, MTOT / 128), 512, SMEM_DYN>>>(h2, wfc2, fc2b, out,
                                                     MTOT, DIM, HIDDEN, x1);
}

// round 15
// speedup vs baseline: 1.5747x; 1.0540x over previous
#include <cuda_runtime.h>
#include <cuda_bf16.h>
#include <math.h>
#include <stdint.h>

#define BZ 32
#define HH 56
#define WW 56
#define DIM 256
#define HEADS 8
#define WS 7
#define SHIFT 3
#define NTOK 49
#define NWIN 64
#define HEAD_DIM 32
#define HIDDEN 1024
#define MTOT (BZ*HH*WW)    // 100352 rows

typedef __nv_bfloat16 bf16;

// ---------------- scratch ----------------------------------------------------
__device__ bf16  g_hwin[(size_t)MTOT * DIM];
__device__ bf16  g_qkv [(size_t)MTOT * 3 * DIM];
__device__ bf16  g_attn[(size_t)MTOT * DIM];
__device__ float g_x1  [(size_t)MTOT * DIM];
__device__ bf16  g_h2  [(size_t)MTOT * HIDDEN];
__device__ bf16  g_wqkv[3 * DIM * DIM];
__device__ bf16  g_wproj[DIM * DIM];
__device__ bf16  g_wfc1[HIDDEN * DIM];
__device__ bf16  g_wfc2[DIM * HIDDEN];
__device__ bf16  g_comb[64 * 8 * 64 * 64];

__device__ __forceinline__ int remap_row(int m) {
    int b    = m / (NWIN * NTOK);
    int rem  = m - b * (NWIN * NTOK);
    int wimg = rem / NTOK;
    int n    = rem - wimg * NTOK;
    int hh = (wimg >> 3) * WS + n / WS + SHIFT; if (hh >= HH) hh -= HH;
    int ww = (wimg & 7) * WS + n % WS + SHIFT;  if (ww >= WW) ww -= WW;
    return b * (HH * WW) + hh * WW + ww;
}

// ---------------- ptx helpers -------------------------------------------------
__device__ __forceinline__ uint32_t smem_u32(const void* p) {
    return (uint32_t)__cvta_generic_to_shared(p);
}
__device__ __forceinline__ void cp16(uint32_t dst, const void* src) {
    asm volatile("cp.async.cg.shared.global [%0], [%1], 16;\n" :: "r"(dst), "l"(src));
}
__device__ __forceinline__ void cp_commit() { asm volatile("cp.async.commit_group;\n"); }
template<int N> __device__ __forceinline__ void cp_wait() {
    asm volatile("cp.async.wait_group %0;\n" :: "n"(N));
}
__device__ __forceinline__ void mbar_init(uint32_t a, uint32_t cnt) {
    asm volatile("mbarrier.init.shared.b64 [%0], %1;" :: "r"(a), "r"(cnt) : "memory");
}
__device__ __forceinline__ void mbar_expect(uint32_t a, uint32_t bytes) {
    asm volatile("mbarrier.arrive.expect_tx.shared.b64 _, [%0], %1;"
                 :: "r"(a), "r"(bytes) : "memory");
}
__device__ __forceinline__ void mbar_wait(uint32_t a, uint32_t parity) {
    asm volatile("{\n\t.reg .pred P;\n"
                 "LAB%=:\n\tmbarrier.try_wait.parity.acquire.cta.shared::cta.b64 P, [%0], %1;\n"
                 "\t@!P bra LAB%=;\n\t}"
                 :: "r"(a), "r"(parity) : "memory");
}
__device__ __forceinline__ void cpbulk(uint32_t dst, const void* src, uint32_t bytes,
                                       uint32_t mbar) {
    asm volatile("cp.async.bulk.shared::cluster.global.mbarrier::complete_tx::bytes "
                 "[%0], [%1], %2, [%3];"
                 :: "r"(dst), "l"(src), "r"(bytes), "r"(mbar) : "memory");
}
__device__ __forceinline__ void ldsm4(uint32_t* r, uint32_t addr) {
    asm volatile("ldmatrix.sync.aligned.m8n8.x4.shared.b16 {%0,%1,%2,%3}, [%4];"
                 : "=r"(r[0]), "=r"(r[1]), "=r"(r[2]), "=r"(r[3]) : "r"(addr));
}
__device__ __forceinline__ void mma_bf16(float* d, const uint32_t* a, const uint32_t* b) {
    asm volatile(
        "mma.sync.aligned.m16n8k16.row.col.f32.bf16.bf16.f32 "
        "{%0,%1,%2,%3}, {%4,%5,%6,%7}, {%8,%9}, {%0,%1,%2,%3};\n"
        : "+f"(d[0]), "+f"(d[1]), "+f"(d[2]), "+f"(d[3])
        : "r"(a[0]), "r"(a[1]), "r"(a[2]), "r"(a[3]), "r"(b[0]), "r"(b[1]));
}
__device__ __forceinline__ uint32_t pack_bf16x2(float a, float b) {
    __nv_bfloat162 h;
    h.x = __float2bfloat16(a); h.y = __float2bfloat16(b);
    return *(uint32_t*)&h;
}

// ---------------- fp32 -> bf16 weight convert (fused, 4 segs) -----------------
__global__ void cvt4_kernel(const float* s0, bf16* d0, int n0,
                            const float* s1, bf16* d1, int n1,
                            const float* s2, bf16* d2, int n2,
                            const float* s3, bf16* d3, int n3) {
    const float* s; bf16* d; int n;
    switch (blockIdx.y) {
        case 0: s = s0; d = d0; n = n0; break;
        case 1: s = s1; d = d1; n = n1; break;
        case 2: s = s2; d = d2; n = n2; break;
        default: s = s3; d = d3; n = n3; break;
    }
    int i = (blockIdx.x * blockDim.x + threadIdx.x) * 4;
    if (i < n) {
        float4 v = *(const float4*)(s + i);
        __nv_bfloat162 p0 = {__float2bfloat16(v.x), __float2bfloat16(v.y)};
        __nv_bfloat162 p1 = {__float2bfloat16(v.z), __float2bfloat16(v.w)};
        *(__nv_bfloat162*)(d + i)     = p0;
        *(__nv_bfloat162*)(d + i + 2) = p1;
    }
}

// ---------------- comb bias precompute ---------------------------------------
__global__ void comb_kernel(const float* __restrict__ rpb,
                            const int* __restrict__ relix,
                            const float* __restrict__ mask,
                            bf16* __restrict__ comb) {
    int w = blockIdx.x, h = blockIdx.y;
    const float* mw = mask + w * (NTOK * NTOK);
    size_t base = ((size_t)(w * 8 + h)) << 12;
    for (int e = threadIdx.x; e < 4096; e += 256) {
        int n = e >> 6, m = e & 63;
        float v = -1e30f;
        if (n < NTOK && m < NTOK)
            v = rpb[relix[n * NTOK + m] * HEADS + h] + mw[n * NTOK + m];
        comb[base + e] = __float2bfloat16(v);
    }
}

// ---------------- LayerNorm (warp per row, bf16 out) -------------------------
template<bool SHIFTMAP>
__global__ void __launch_bounds__(256) ln_kernel(const float* __restrict__ x,
                                                 const float* __restrict__ gw,
                                                 const float* __restrict__ gb,
                                                 bf16* __restrict__ out) {
    int warp = threadIdx.x >> 5, lane = threadIdx.x & 31;
    int m = blockIdx.x * 8 + warp;
    const float* xr;
    if (SHIFTMAP) {
        int r = remap_row(m);
        xr = x + (size_t)r * DIM;
    } else {
        xr = x + (size_t)m * DIM;
    }
    float4 v0 = *(const float4*)(xr + lane * 4);
    float4 v1 = *(const float4*)(xr + 128 + lane * 4);
    float s  = v0.x + v0.y + v0.z + v0.w + v1.x + v1.y + v1.z + v1.w;
    float sq = v0.x*v0.x + v0.y*v0.y + v0.z*v0.z + v0.w*v0.w
             + v1.x*v1.x + v1.y*v1.y + v1.z*v1.z + v1.w*v1.w;
    #pragma unroll
    for (int o = 16; o; o >>= 1) {
        s  += __shfl_xor_sync(0xffffffffu, s,  o);
        sq += __shfl_xor_sync(0xffffffffu, sq, o);
    }
    float mu  = s * (1.0f / DIM);
    float var = sq * (1.0f / DIM) - mu * mu;
    float rs  = rsqrtf(var + 1e-5f);
    float4 w0 = *(const float4*)(gw + lane * 4);
    float4 w1 = *(const float4*)(gw + 128 + lane * 4);
    float4 b0 = *(const float4*)(gb + lane * 4);
    float4 b1 = *(const float4*)(gb + 128 + lane * 4);
    bf16* orow = out + (size_t)m * DIM;
    __nv_bfloat162 p;
    p = {__float2bfloat16((v0.x-mu)*rs*w0.x+b0.x), __float2bfloat16((v0.y-mu)*rs*w0.y+b0.y)};
    *(__nv_bfloat162*)(orow + lane*4)     = p;
    p = {__float2bfloat16((v0.z-mu)*rs*w0.z+b0.z), __float2bfloat16((v0.w-mu)*rs*w0.w+b0.w)};
    *(__nv_bfloat162*)(orow + lane*4 + 2) = p;
    p = {__float2bfloat16((v1.x-mu)*rs*w1.x+b1.x), __float2bfloat16((v1.y-mu)*rs*w1.y+b1.y)};
    *(__nv_bfloat162*)(orow + 128 + lane*4)     = p;
    p = {__float2bfloat16((v1.z-mu)*rs*w1.z+b1.z), __float2bfloat16((v1.w-mu)*rs*w1.w+b1.w)};
    *(__nv_bfloat162*)(orow + 128 + lane*4 + 2) = p;
}

// ============ persistent-B GEMM (K=256), bulk-copy A stream ===================
// 512 threads, warp grid 4(m)x4(n), warp tile 32x64.
// EPI: 0=+bias->bf16  1=+bias,GELU->bf16  2=+bias,remap,+res->f32
//      7=+bias,remap,+res->f32 AND fused LayerNorm->bf16 (requires grid.x==1)
#define PMB 0
#define PA_OFF 64
#define PA_SROW 144
#define PA_STAGE (128 * PA_SROW)
#define PB_SROW 528
#define PB_OFF (PA_OFF + 3 * PA_STAGE)      // 55360
#define RS_OFF (PB_OFF + 256 * PB_SROW)     // 190528 (rsum: 4x128 float2 = 4KB)
#define LNW_OFF (RS_OFF + 4096)             // gw/gb: 512 floats = 2KB
#define PSMEM (LNW_OFF + 2048)              // 196672

template<int EPI>
__global__ void __launch_bounds__(512, 1) pgemm(const bf16* __restrict__ A,
                                               const bf16* __restrict__ Bm,
                                               const float* __restrict__ bias,
                                               void* __restrict__ Cv,
                                               int M, int N, int lda, int ldb,
                                               const float* __restrict__ res,
                                               const float* __restrict__ lnw,
                                               const float* __restrict__ lnb,
                                               bf16* __restrict__ out2,
                                               int GY) {
    extern __shared__ __align__(128) char smem[];
    uint32_t sbase = smem_u32(smem);
    int tid = threadIdx.x;
    int warp = tid >> 5, lane = tid & 31;
    int bn = blockIdx.x, gy = blockIdx.y;
    int warpM = (warp & 3) * 32;
    int warpN = (warp >> 2) * 64;
    int r = lane >> 2, c = lane & 3;
    int mt = M >> 7;

    if (tid == 0) {
        mbar_init(sbase + PMB + 0, 128);
        mbar_init(sbase + PMB + 8, 128);
        mbar_init(sbase + PMB + 16, 128);
    }
    uint32_t sB = sbase + PB_OFF;
    {
        const bf16* Bbase = Bm + (size_t)(bn * 256) * ldb;
        #pragma unroll
        for (int rpt = 0; rpt < 16; rpt++) {
            int ch = tid + rpt * 512;
            int row = ch >> 5, col = ch & 31;
            cp16(sB + row * PB_SROW + col * 16, Bbase + (size_t)row * ldb + col * 8);
        }
    }
    if (EPI == 7 && tid < 256) {
        ((float*)(smem + LNW_OFF))[tid]       = lnw[tid];
        ((float*)(smem + LNW_OFF))[256 + tid] = lnb[tid];
    }
    cp_commit();
    __syncthreads();   // mbarrier init + LN weights visible

    uint32_t aoff = (uint32_t)((lane & 15) * PA_SROW + (lane >> 4) * 16);
    uint32_t boff = (uint32_t)(((lane & 7) + ((lane >> 4) << 3)) * PB_SROW
                               + ((lane & 8) ? 16 : 0));

    int ntiles = (mt - gy + GY - 1) / GY;
    int nj = ntiles * 4;

#define FILLA(s, j) do { \
    if (tid < 128) { \
        const bf16* Ab = A + (size_t)(gy + ((j) >> 2) * GY) * 128 * lda \
                         + ((j) & 3) * 64 + (size_t)tid * lda; \
        uint32_t mb = sbase + PMB + (s) * 8; \
        mbar_expect(mb, 128); \
        cpbulk(sbase + PA_OFF + (s) * PA_STAGE + tid * PA_SROW, Ab, 128, mb); \
    } \
} while (0)

    FILLA(0, 0);
    if (nj > 1) FILLA(1, 1);
    cp_wait<0>();

    for (int t = 0; t < ntiles; t++) {
        int bm = gy + t * GY;
        float acc[2][8][4];
        #pragma unroll
        for (int mi = 0; mi < 2; mi++)
            #pragma unroll
            for (int ni = 0; ni < 8; ni++)
                #pragma unroll
                for (int q = 0; q < 4; q++) acc[mi][ni][q] = 0.0f;

        #pragma unroll
        for (int s4 = 0; s4 < 4; s4++) {
            int j = t * 4 + s4;
            int st = j % 3;
            mbar_wait(sbase + PMB + st * 8, (uint32_t)((j / 3) & 1));
            __syncthreads();
            if (j + 2 < nj) FILLA((j + 2) % 3, j + 2);

            uint32_t As = sbase + PA_OFF + st * PA_STAGE;
            #pragma unroll
            for (int kk = 0; kk < 4; kk++) {
                int k16 = s4 * 4 + kk;
                uint32_t af[2][4], bfr[4][4];
                #pragma unroll
                for (int mi = 0; mi < 2; mi++)
                    ldsm4(af[mi], As + (uint32_t)((warpM + mi * 16) * PA_SROW + kk * 32) + aoff);
                #pragma unroll
                for (int p = 0; p < 4; p++)
                    ldsm4(bfr[p], sB + (uint32_t)((warpN + p * 16) * PB_SROW + k16 * 32) + boff);
                #pragma unroll
                for (int mi = 0; mi < 2; mi++)
                    #pragma unroll
                    for (int ni = 0; ni < 8; ni++)
                        mma_bf16(acc[mi][ni], af[mi], &bfr[ni >> 1][(ni & 1) * 2]);
            }
        }

        if (EPI == 7) {
            // pass 1: x1 = mma + bias + res (remap scatter), accumulate row sums
            float2* rsum = (float2*)(smem + RS_OFF);
            const float* gws = (const float*)(smem + LNW_OFF);
            const float* gbs = gws + 256;
            int wn = warp >> 2;
            #pragma unroll
            for (int mi = 0; mi < 2; mi++) {
                #pragma unroll
                for (int half = 0; half < 2; half++) {
                    int row = bm * 128 + warpM + mi * 16 + r + half * 8;
                    int orow = remap_row(row);
                    const float* rr = res + (size_t)orow * N;
                    float* cp = (float*)Cv + (size_t)orow * N;
                    float s = 0.0f, sq = 0.0f;
                    #pragma unroll
                    for (int ni = 0; ni < 8; ni++) {
                        int col = warpN + ni * 8 + 2 * c;
                        float v0 = acc[mi][ni][half * 2 + 0] + bias[col] + rr[col];
                        float v1 = acc[mi][ni][half * 2 + 1] + bias[col + 1] + rr[col + 1];
                        acc[mi][ni][half * 2 + 0] = v0;
                        acc[mi][ni][half * 2 + 1] = v1;
                        *(float2*)(cp + col) = make_float2(v0, v1);
                        s += v0 + v1;
                        sq += v0 * v0 + v1 * v1;
                    }
                    s  += __shfl_xor_sync(0xffffffffu, s, 1);
                    s  += __shfl_xor_sync(0xffffffffu, s, 2);
                    sq += __shfl_xor_sync(0xffffffffu, sq, 1);
                    sq += __shfl_xor_sync(0xffffffffu, sq, 2);
                    if ((lane & 3) == 0) {
                        int lr = warpM + mi * 16 + r + half * 8;
                        rsum[wn * 128 + lr] = make_float2(s, sq);
                    }
                }
            }
            __syncthreads();
            // pass 2: apply LN -> bf16 out2
            #pragma unroll
            for (int mi = 0; mi < 2; mi++) {
                #pragma unroll
                for (int half = 0; half < 2; half++) {
                    int lr = warpM + mi * 16 + r + half * 8;
                    float S = 0.0f, SQ = 0.0f;
                    #pragma unroll
                    for (int g = 0; g < 4; g++) {
                        float2 pp = rsum[g * 128 + lr];
                        S += pp.x; SQ += pp.y;
                    }
                    float mu  = S * (1.0f / 256.0f);
                    float var = SQ * (1.0f / 256.0f) - mu * mu;
                    float rsg = rsqrtf(var + 1e-5f);
                    int orow = remap_row(bm * 128 + lr);
                    bf16* op = out2 + (size_t)orow * 256;
                    #pragma unroll
                    for (int ni = 0; ni < 8; ni++) {
                        int col = warpN + ni * 8 + 2 * c;
                        float v0 = (acc[mi][ni][half * 2 + 0] - mu) * rsg * gws[col] + gbs[col];
                        float v1 = (acc[mi][ni][half * 2 + 1] - mu) * rsg * gws[col + 1] + gbs[col + 1];
                        __nv_bfloat162 pk = {__float2bfloat16(v0), __float2bfloat16(v1)};
                        *(__nv_bfloat162*)(op + col) = pk;
                    }
                }
            }
        } else {
            #pragma unroll
            for (int mi = 0; mi < 2; mi++) {
                #pragma unroll
                for (int half = 0; half < 2; half++) {
                    int row = bm * 128 + warpM + mi * 16 + r + half * 8;
                    int orow = row;
                    if (EPI == 2) orow = remap_row(row);
                    const float* rr = (EPI == 2) ? res + (size_t)orow * N : nullptr;
                    #pragma unroll
                    for (int ni = 0; ni < 8; ni++) {
                        int col = bn * 256 + warpN + ni * 8 + 2 * c;
                        float v0 = acc[mi][ni][half * 2 + 0] + bias[col];
                        float v1 = acc[mi][ni][half * 2 + 1] + bias[col + 1];
                        if (EPI == 1) {
                            v0 = 0.5f * v0 * (1.0f + erff(v0 * 0.70710678118654752f));
                            v1 = 0.5f * v1 * (1.0f + erff(v1 * 0.70710678118654752f));
                        }
                        if (EPI == 2) { v0 += rr[col]; v1 += rr[col + 1]; }
                        if (EPI == 0 || EPI == 1) {
                            bf16* cp = (bf16*)Cv + (size_t)orow * N;
                            __nv_bfloat162 pk = {__float2bfloat16(v0), __float2bfloat16(v1)};
                            *(__nv_bfloat162*)(cp + col) = pk;
                        } else {
                            float* cp = (float*)Cv + (size_t)orow * N;
                            *(float2*)(cp + col) = make_float2(v0, v1);
                        }
                    }
                }
            }
        }
    }
#undef FILLA
}

// ---------------- streaming GEMM (fc2, K=1024), cp16 (R11-proven) ------------
#define FSROW 144
#define FASTAGE (128 * FSROW)
#define FBSTAGE (256 * FSROW)
#define FSTAGEB (FASTAGE + FBSTAGE)
#define FNSTAGE 3
#define FSMEM (FNSTAGE * FSTAGEB)   // 165888

template<int EPI>
__global__ void __launch_bounds__(512, 1) bgemm(const bf16* __restrict__ A,
                                               const bf16* __restrict__ Bm,
                                               const float* __restrict__ bias,
                                               void* __restrict__ Cv,
                                               int M, int N, int K,
                                               const float* __restrict__ res) {
    extern __shared__ __align__(16) char smem[];
    uint32_t sbase = smem_u32(smem);
    int tid = threadIdx.x;
    int bn = blockIdx.x, bm = blockIdx.y;
    int warp = tid >> 5, lane = tid & 31;
    int warpM = (warp & 3) * 32;
    int warpN = (warp >> 2) * 64;
    int r = lane >> 2, c = lane & 3;

    int arw[2], acc_[2], brw[4], bcc[4];
    #pragma unroll
    for (int rpt = 0; rpt < 2; rpt++) {
        int ch = tid + rpt * 512;
        arw[rpt] = ch >> 3; acc_[rpt] = ch & 7;
    }
    #pragma unroll
    for (int rpt = 0; rpt < 4; rpt++) {
        int ch = tid + rpt * 512;
        brw[rpt] = ch >> 3; bcc[rpt] = ch & 7;
    }
    const bf16* Abase = A  + (size_t)(bm * 128) * K;
    const bf16* Bbase = Bm + (size_t)(bn * 256) * K;

    uint32_t aoff = (uint32_t)((lane & 15) * FSROW + (lane >> 4) * 16);
    uint32_t boff = (uint32_t)(((lane & 7) + ((lane >> 4) << 3)) * FSROW + ((lane & 8) ? 16 : 0));

    float acc[2][8][4];
    #pragma unroll
    for (int mi = 0; mi < 2; mi++)
        #pragma unroll
        for (int ni = 0; ni < 8; ni++)
            #pragma unroll
            for (int t = 0; t < 4; t++) acc[mi][ni][t] = 0.0f;

#define FILL(s, k0) do { \
    uint32_t ab = sbase + (s) * FSTAGEB; \
    uint32_t bb = ab + FASTAGE; \
    _Pragma("unroll") \
    for (int rpt = 0; rpt < 2; rpt++) \
        cp16(ab + arw[rpt] * FSROW + acc_[rpt] * 16, \
             Abase + (size_t)arw[rpt] * K + (k0) + acc_[rpt] * 8); \
    _Pragma("unroll") \
    for (int rpt = 0; rpt < 4; rpt++) \
        cp16(bb + brw[rpt] * FSROW + bcc[rpt] * 16, \
             Bbase + (size_t)brw[rpt] * K + (k0) + bcc[rpt] * 8); \
} while (0)

    int nk = K >> 6;
    FILL(0, 0);  cp_commit();
    FILL(1, 64); cp_commit();

    int stage = 0, fstage = 2;
    for (int i = 0; i < nk; i++) {
        cp_wait<1>();
        __syncthreads();
        if (i + 2 < nk) {
            FILL(fstage, (i + 2) * 64);
        }
        cp_commit();

        uint32_t Ab = sbase + stage * FSTAGEB;
        uint32_t Bb = Ab + FASTAGE;

        #pragma unroll
        for (int kk = 0; kk < 4; kk++) {
            uint32_t af[2][4], bfr[4][4];
            #pragma unroll
            for (int mi = 0; mi < 2; mi++)
                ldsm4(af[mi], Ab + (uint32_t)((warpM + mi * 16) * FSROW + kk * 32) + aoff);
            #pragma unroll
            for (int p = 0; p < 4; p++)
                ldsm4(bfr[p], Bb + (uint32_t)((warpN + p * 16) * FSROW + kk * 32) + boff);
            #pragma unroll
            for (int mi = 0; mi < 2; mi++)
                #pragma unroll
                for (int ni = 0; ni < 8; ni++)
                    mma_bf16(acc[mi][ni], af[mi], &bfr[ni >> 1][(ni & 1) * 2]);
        }

        stage = (stage + 1 == FNSTAGE) ? 0 : stage + 1;
        fstage = (fstage + 1 == FNSTAGE) ? 0 : fstage + 1;
    }

    #pragma unroll
    for (int mi = 0; mi < 2; mi++) {
        #pragma unroll
        for (int half = 0; half < 2; half++) {
            int row = bm * 128 + warpM + mi * 16 + r + half * 8;
            const float* rr = res + (size_t)row * N;
            #pragma unroll
            for (int ni = 0; ni < 8; ni++) {
                int col = bn * 256 + warpN + ni * 8 + 2 * c;
                float v0 = acc[mi][ni][half * 2 + 0] + bias[col] + rr[col];
                float v1 = acc[mi][ni][half * 2 + 1] + bias[col + 1] + rr[col + 1];
                float* cp = (float*)Cv + (size_t)row * N;
                *(float2*)(cp + col) = make_float2(v0, v1);
            }
        }
    }
#undef FILL
}

// ---------------- tensor-core windowed attention ------------------------------
__global__ void __launch_bounds__(256) attn_tc(const bf16* __restrict__ qkv,
                                               const bf16* __restrict__ comb,
                                               bf16* __restrict__ out) {
    __shared__ __align__(16) bf16 sQ[2][64 * 40];
    __shared__ __align__(16) bf16 sK[2][64 * 40];
    __shared__ __align__(16) bf16 sVT[2][32 * 72];
    __shared__ __align__(16) bf16 sB[2][64 * 72];

    int tid = threadIdx.x;
    int win = blockIdx.x;
    int hg  = blockIdx.y * 2;
    int w64 = win & 63;

    uint32_t* vz = (uint32_t*)sVT;
    for (int i = tid; i < 2 * 32 * 72 / 2; i += 256) vz[i] = 0;
    for (int i = tid; i < 600; i += 256) {
        int h = i / 300, rm = i % 300;
        int row = 49 + rm / 20, w = rm % 20;
        ((uint32_t*)sQ)[h * 1280 + row * 20 + w] = 0;
        ((uint32_t*)sK)[h * 1280 + row * 20 + w] = 0;
    }
    __syncthreads();

    for (int i = tid; i < 392; i += 256) {
        int h = i / 196, rm = i % 196;
        int tok = rm >> 2, ch = rm & 3;
        const bf16* src = qkv + (size_t)(win * 49 + tok) * 768 + (hg + h) * 32 + ch * 8;
        *(uint4*)((char*)sQ + h * 5120 + tok * 80 + ch * 16) = *(const uint4*)src;
        *(uint4*)((char*)sK + h * 5120 + tok * 80 + ch * 16) = *(const uint4*)(src + 256);
    }
    for (int i = tid; i < 1568; i += 256) {
        int h = i / 784, rm = i % 784;
        int tok = rm / 16, dp = (rm % 16) * 2;
        __nv_bfloat162 v = *(const __nv_bfloat162*)(qkv + (size_t)(win * 49 + tok) * 768
                                                    + 512 + (hg + h) * 32 + dp);
        *(bf16*)((char*)sVT + h * 4608 + dp * 144 + tok * 2)       = v.x;
        *(bf16*)((char*)sVT + h * 4608 + (dp + 1) * 144 + tok * 2) = v.y;
    }
    for (int i = tid; i < 1024; i += 256) {
        int h = i >> 9, rm = i & 511;
        int n = rm >> 3, ch = rm & 7;
        const bf16* src = comb + (((size_t)((w64 * 8 + hg + h) * 64 + n)) << 6) + ch * 8;
        *(uint4*)((char*)sB + h * 9216 + n * 144 + ch * 16) = *(const uint4*)src;
    }
    __syncthreads();

    int warp = tid >> 5, lane = tid & 31;
    int head = warp >> 2;
    int rowbase = (warp & 3) * 16;

    uint32_t Qb = smem_u32(sQ) + head * 5120;
    uint32_t Kb = smem_u32(sK) + head * 5120;
    uint32_t Vb = smem_u32(sVT) + head * 4608;
    uint32_t Bb = smem_u32(sB) + head * 9216;

    uint32_t aoff80  = (uint32_t)((lane & 15) * 80 + (lane >> 4) * 16);
    uint32_t aoff144 = (uint32_t)((lane & 15) * 144 + (lane >> 4) * 16);
    uint32_t boff80  = (uint32_t)(((lane & 7) + ((lane >> 4) << 3)) * 80 + ((lane & 8) ? 16 : 0));
    uint32_t boff144 = (uint32_t)(((lane & 7) + ((lane >> 4) << 3)) * 144 + ((lane & 8) ? 16 : 0));

    float sacc[8][4];
    #pragma unroll
    for (int ni = 0; ni < 8; ni++)
        #pragma unroll
        for (int t = 0; t < 4; t++) sacc[ni][t] = 0.0f;

    #pragma unroll
    for (int ks = 0; ks < 2; ks++) {
        uint32_t aq[4], bk[4][4];
        ldsm4(aq, Qb + (uint32_t)(rowbase * 80 + ks * 32) + aoff80);
        #pragma unroll
        for (int p = 0; p < 4; p++)
            ldsm4(bk[p], Kb + (uint32_t)(p * 16 * 80 + ks * 32) + boff80);
        #pragma unroll
        for (int ni = 0; ni < 8; ni++)
            mma_bf16(sacc[ni], aq, &bk[ni >> 1][(ni & 1) * 2]);
    }

    const float scale = 0.17677669529663687f;
    #pragma unroll
    for (int cg = 0; cg < 4; cg++) {
        uint32_t bb[4];
        ldsm4(bb, Bb + (uint32_t)(rowbase * 144 + cg * 32) + aoff144);
        float2 f;
        f = __bfloat1622float2(*(__nv_bfloat162*)&bb[0]);
        sacc[2*cg][0] = sacc[2*cg][0] * scale + f.x;
        sacc[2*cg][1] = sacc[2*cg][1] * scale + f.y;
        f = __bfloat1622float2(*(__nv_bfloat162*)&bb[1]);
        sacc[2*cg][2] = sacc[2*cg][2] * scale + f.x;
        sacc[2*cg][3] = sacc[2*cg][3] * scale + f.y;
        f = __bfloat1622float2(*(__nv_bfloat162*)&bb[2]);
        sacc[2*cg+1][0] = sacc[2*cg+1][0] * scale + f.x;
        sacc[2*cg+1][1] = sacc[2*cg+1][1] * scale + f.y;
        f = __bfloat1622float2(*(__nv_bfloat162*)&bb[3]);
        sacc[2*cg+1][2] = sacc[2*cg+1][2] * scale + f.x;
        sacc[2*cg+1][3] = sacc[2*cg+1][3] * scale + f.y;
    }

    #pragma unroll
    for (int hf = 0; hf < 2; hf++) {
        int i0 = hf * 2;
        float mx = -1e30f;
        #pragma unroll
        for (int ni = 0; ni < 8; ni++)
            mx = fmaxf(mx, fmaxf(sacc[ni][i0], sacc[ni][i0 + 1]));
        mx = fmaxf(mx, __shfl_xor_sync(0xffffffffu, mx, 1));
        mx = fmaxf(mx, __shfl_xor_sync(0xffffffffu, mx, 2));
        float sum = 0.0f;
        #pragma unroll
        for (int ni = 0; ni < 8; ni++) {
            float e0 = expf(sacc[ni][i0] - mx);
            float e1 = expf(sacc[ni][i0 + 1] - mx);
            sacc[ni][i0] = e0; sacc[ni][i0 + 1] = e1;
            sum += e0 + e1;
        }
        sum += __shfl_xor_sync(0xffffffffu, sum, 1);
        sum += __shfl_xor_sync(0xffffffffu, sum, 2);
        float inv = 1.0f / sum;
        #pragma unroll
        for (int ni = 0; ni < 8; ni++) {
            sacc[ni][i0] *= inv; sacc[ni][i0 + 1] *= inv;
        }
    }

    uint32_t pa[4][4];
    #pragma unroll
    for (int ks = 0; ks < 4; ks++) {
        pa[ks][0] = pack_bf16x2(sacc[2*ks][0],   sacc[2*ks][1]);
        pa[ks][1] = pack_bf16x2(sacc[2*ks][2],   sacc[2*ks][3]);
        pa[ks][2] = pack_bf16x2(sacc[2*ks+1][0], sacc[2*ks+1][1]);
        pa[ks][3] = pack_bf16x2(sacc[2*ks+1][2], sacc[2*ks+1][3]);
    }

    float oacc[4][4];
    #pragma unroll
    for (int ni = 0; ni < 4; ni++)
        #pragma unroll
        for (int t = 0; t < 4; t++) oacc[ni][t] = 0.0f;

    #pragma unroll
    for (int ks = 0; ks < 4; ks++) {
        uint32_t bv[2][4];
        #pragma unroll
        for (int p = 0; p < 2; p++)
            ldsm4(bv[p], Vb + (uint32_t)(p * 16 * 144 + ks * 32) + boff144);
        #pragma unroll
        for (int ni = 0; ni < 4; ni++)
            mma_bf16(oacc[ni], pa[ks], &bv[ni >> 1][(ni & 1) * 2]);
    }

    int gh = hg + head;
    int r0 = rowbase + (lane >> 2);
    #pragma unroll
    for (int ni = 0; ni < 4; ni++) {
        int col = gh * 32 + ni * 8 + (lane & 3) * 2;
        if (r0 < NTOK) {
            __nv_bfloat162 pk = {__float2bfloat16(oacc[ni][0]), __float2bfloat16(oacc[ni][1])};
            *(__nv_bfloat162*)(out + (size_t)(win * 49 + r0) * 256 + col) = pk;
        }
        if (r0 + 8 < NTOK) {
            __nv_bfloat162 pk = {__float2bfloat16(oacc[ni][2]), __float2bfloat16(oacc[ni][3])};
            *(__nv_bfloat162*)(out + (size_t)(win * 49 + r0 + 8) * 256 + col) = pk;
        }
    }
}

// ---------------- launcher ---------------------------------------------------
extern "C" void kernel_launch(void* const* d_in, const int* in_sizes, int n_in,
                              void* d_out, int out_size) {
    const float* x     = (const float*)d_in[0];
    const float* n1w   = (const float*)d_in[1];
    const float* n1b   = (const float*)d_in[2];
    const float* qkvw  = (const float*)d_in[3];
    const float* qkvb  = (const float*)d_in[4];
    const float* rpb   = (const float*)d_in[5];
    const float* projw = (const float*)d_in[6];
    const float* projb = (const float*)d_in[7];
    const float* n2w   = (const float*)d_in[8];
    const float* n2b   = (const float*)d_in[9];
    const float* fc1w  = (const float*)d_in[10];
    const float* fc1b  = (const float*)d_in[11];
    const float* fc2w  = (const float*)d_in[12];
    const float* fc2b  = (const float*)d_in[13];
    const int*   relix = (const int*)d_in[14];
    const float* amask = (const float*)d_in[15];
    float* out = (float*)d_out;

    bf16 *hwin, *qkv, *attn, *h2, *wqkv, *wproj, *wfc1, *wfc2, *comb;
    float *x1;
    cudaGetSymbolAddress((void**)&hwin, g_hwin);
    cudaGetSymbolAddress((void**)&qkv,  g_qkv);
    cudaGetSymbolAddress((void**)&attn, g_attn);
    cudaGetSymbolAddress((void**)&x1,   g_x1);
    cudaGetSymbolAddress((void**)&h2,   g_h2);
    cudaGetSymbolAddress((void**)&wqkv, g_wqkv);
    cudaGetSymbolAddress((void**)&wproj, g_wproj);
    cudaGetSymbolAddress((void**)&wfc1, g_wfc1);
    cudaGetSymbolAddress((void**)&wfc2, g_wfc2);
    cudaGetSymbolAddress((void**)&comb, g_comb);

    cudaFuncSetAttribute(pgemm<0>, cudaFuncAttributeMaxDynamicSharedMemorySize, PSMEM);
    cudaFuncSetAttribute(pgemm<1>, cudaFuncAttributeMaxDynamicSharedMemorySize, PSMEM);
    cudaFuncSetAttribute(pgemm<7>, cudaFuncAttributeMaxDynamicSharedMemorySize, PSMEM);
    cudaFuncSetAttribute(bgemm<3>, cudaFuncAttributeMaxDynamicSharedMemorySize, FSMEM);

    cvt4_kernel<<<dim3(DIM * HIDDEN / 4 / 256, 4), 256>>>(
        qkvw, wqkv, 3 * DIM * DIM,
        projw, wproj, DIM * DIM,
        fc1w, wfc1, HIDDEN * DIM,
        fc2w, wfc2, DIM * HIDDEN);
    comb_kernel<<<dim3(64, 8), 256>>>(rpb, relix, amask, comb);

    // 1. LN1 + shift + window-partition (bf16 out)
    ln_kernel<true><<<MTOT / 8, 256>>>(x, n1w, n1b, hwin);
    // 2. QKV GEMM (persistent-B, bulk A) -> bf16
    pgemm<0><<<dim3(3, 49), 512, PSMEM>>>(hwin, wqkv, qkvb, qkv, MTOT, 3 * DIM,
                                          DIM, DIM, nullptr, nullptr, nullptr,
                                          nullptr, 49);
    // 3. tensor-core windowed attention
    attn_tc<<<dim3(BZ * NWIN, 4), 256>>>(qkv, comb, attn);
    // 4. proj GEMM + remap + residual -> x1(f32) AND fused LN2 -> hwin(bf16)
    pgemm<7><<<dim3(1, 148), 512, PSMEM>>>(attn, wproj, projb, x1, MTOT, DIM,
                                           DIM, DIM, x, n2w, n2b, hwin, 148);
    // 5. FC1 + GELU (persistent-B) -> bf16
    pgemm<1><<<dim3(4, 37), 512, PSMEM>>>(hwin, wfc1, fc1b, h2, MTOT, HIDDEN,
                                          DIM, DIM, nullptr, nullptr, nullptr,
                                          nullptr, 37);
    // 6. FC2 + residual -> out (f32)  (streaming cp16, K=1024)
    bgemm<3><<<dim3(1, MTOT / 128), 512, FSMEM>>>(h2, wfc2, fc2b, out,
                                                  MTOT, DIM, HIDDEN, x1);
}

// round 16
// speedup vs baseline: 1.5750x; 1.0002x over previous
#include <cuda_runtime.h>
#include <cuda_bf16.h>
#include <math.h>
#include <stdint.h>

#define BZ 32
#define HH 56
#define WW 56
#define DIM 256
#define HEADS 8
#define WS 7
#define SHIFT 3
#define NTOK 49
#define NWIN 64
#define HEAD_DIM 32
#define HIDDEN 1024
#define MTOT (BZ*HH*WW)    // 100352 rows

typedef __nv_bfloat16 bf16;

// ---------------- scratch ----------------------------------------------------
__device__ bf16  g_hwin[(size_t)MTOT * DIM];
__device__ bf16  g_qkv [(size_t)MTOT * 3 * DIM];
__device__ bf16  g_attn[(size_t)MTOT * DIM];
__device__ float g_x1  [(size_t)MTOT * DIM];
__device__ bf16  g_h2  [(size_t)MTOT * HIDDEN];
__device__ bf16  g_wqkv[3 * DIM * DIM];
__device__ bf16  g_wproj[DIM * DIM];
__device__ bf16  g_wfc1[HIDDEN * DIM];
__device__ bf16  g_wfc2[DIM * HIDDEN];
__device__ bf16  g_comb[64 * 8 * 64 * 64];

__device__ __forceinline__ int remap_row(int m) {
    int b    = m / (NWIN * NTOK);
    int rem  = m - b * (NWIN * NTOK);
    int wimg = rem / NTOK;
    int n    = rem - wimg * NTOK;
    int hh = (wimg >> 3) * WS + n / WS + SHIFT; if (hh >= HH) hh -= HH;
    int ww = (wimg & 7) * WS + n % WS + SHIFT;  if (ww >= WW) ww -= WW;
    return b * (HH * WW) + hh * WW + ww;
}

// ---------------- ptx helpers -------------------------------------------------
__device__ __forceinline__ uint32_t smem_u32(const void* p) {
    return (uint32_t)__cvta_generic_to_shared(p);
}
__device__ __forceinline__ void cp16(uint32_t dst, const void* src) {
    asm volatile("cp.async.cg.shared.global [%0], [%1], 16;\n" :: "r"(dst), "l"(src));
}
__device__ __forceinline__ void cp_commit() { asm volatile("cp.async.commit_group;\n"); }
template<int N> __device__ __forceinline__ void cp_wait() {
    asm volatile("cp.async.wait_group %0;\n" :: "n"(N));
}
__device__ __forceinline__ void mbar_init(uint32_t a, uint32_t cnt) {
    asm volatile("mbarrier.init.shared.b64 [%0], %1;" :: "r"(a), "r"(cnt) : "memory");
}
__device__ __forceinline__ void mbar_expect(uint32_t a, uint32_t bytes) {
    asm volatile("mbarrier.arrive.expect_tx.shared.b64 _, [%0], %1;"
                 :: "r"(a), "r"(bytes) : "memory");
}
__device__ __forceinline__ void mbar_wait(uint32_t a, uint32_t parity) {
    asm volatile("{\n\t.reg .pred P;\n"
                 "LAB%=:\n\tmbarrier.try_wait.parity.acquire.cta.shared::cta.b64 P, [%0], %1;\n"
                 "\t@!P bra LAB%=;\n\t}"
                 :: "r"(a), "r"(parity) : "memory");
}
__device__ __forceinline__ void cpbulk(uint32_t dst, const void* src, uint32_t bytes,
                                       uint32_t mbar) {
    asm volatile("cp.async.bulk.shared::cluster.global.mbarrier::complete_tx::bytes "
                 "[%0], [%1], %2, [%3];"
                 :: "r"(dst), "l"(src), "r"(bytes), "r"(mbar) : "memory");
}
__device__ __forceinline__ void ldsm4(uint32_t* r, uint32_t addr) {
    asm volatile("ldmatrix.sync.aligned.m8n8.x4.shared.b16 {%0,%1,%2,%3}, [%4];"
                 : "=r"(r[0]), "=r"(r[1]), "=r"(r[2]), "=r"(r[3]) : "r"(addr));
}
__device__ __forceinline__ void mma_bf16(float* d, const uint32_t* a, const uint32_t* b) {
    asm volatile(
        "mma.sync.aligned.m16n8k16.row.col.f32.bf16.bf16.f32 "
        "{%0,%1,%2,%3}, {%4,%5,%6,%7}, {%8,%9}, {%0,%1,%2,%3};\n"
        : "+f"(d[0]), "+f"(d[1]), "+f"(d[2]), "+f"(d[3])
        : "r"(a[0]), "r"(a[1]), "r"(a[2]), "r"(a[3]), "r"(b[0]), "r"(b[1]));
}
__device__ __forceinline__ uint32_t pack_bf16x2(float a, float b) {
    __nv_bfloat162 h;
    h.x = __float2bfloat16(a); h.y = __float2bfloat16(b);
    return *(uint32_t*)&h;
}

// ---------------- fp32 -> bf16 weight convert (fused, 4 segs) -----------------
__global__ void cvt4_kernel(const float* s0, bf16* d0, int n0,
                            const float* s1, bf16* d1, int n1,
                            const float* s2, bf16* d2, int n2,
                            const float* s3, bf16* d3, int n3) {
    const float* s; bf16* d; int n;
    switch (blockIdx.y) {
        case 0: s = s0; d = d0; n = n0; break;
        case 1: s = s1; d = d1; n = n1; break;
        case 2: s = s2; d = d2; n = n2; break;
        default: s = s3; d = d3; n = n3; break;
    }
    int i = (blockIdx.x * blockDim.x + threadIdx.x) * 4;
    if (i < n) {
        float4 v = *(const float4*)(s + i);
        __nv_bfloat162 p0 = {__float2bfloat16(v.x), __float2bfloat16(v.y)};
        __nv_bfloat162 p1 = {__float2bfloat16(v.z), __float2bfloat16(v.w)};
        *(__nv_bfloat162*)(d + i)     = p0;
        *(__nv_bfloat162*)(d + i + 2) = p1;
    }
}

// ---------------- comb bias precompute ---------------------------------------
__global__ void comb_kernel(const float* __restrict__ rpb,
                            const int* __restrict__ relix,
                            const float* __restrict__ mask,
                            bf16* __restrict__ comb) {
    int w = blockIdx.x, h = blockIdx.y;
    const float* mw = mask + w * (NTOK * NTOK);
    size_t base = ((size_t)(w * 8 + h)) << 12;
    for (int e = threadIdx.x; e < 4096; e += 256) {
        int n = e >> 6, m = e & 63;
        float v = -1e30f;
        if (n < NTOK && m < NTOK)
            v = rpb[relix[n * NTOK + m] * HEADS + h] + mw[n * NTOK + m];
        comb[base + e] = __float2bfloat16(v);
    }
}

// ---------------- LayerNorm (warp per row, bf16 out) -------------------------
template<bool SHIFTMAP>
__global__ void __launch_bounds__(256) ln_kernel(const float* __restrict__ x,
                                                 const float* __restrict__ gw,
                                                 const float* __restrict__ gb,
                                                 bf16* __restrict__ out) {
    int warp = threadIdx.x >> 5, lane = threadIdx.x & 31;
    int m = blockIdx.x * 8 + warp;
    const float* xr;
    if (SHIFTMAP) {
        int r = remap_row(m);
        xr = x + (size_t)r * DIM;
    } else {
        xr = x + (size_t)m * DIM;
    }
    float4 v0 = *(const float4*)(xr + lane * 4);
    float4 v1 = *(const float4*)(xr + 128 + lane * 4);
    float s  = v0.x + v0.y + v0.z + v0.w + v1.x + v1.y + v1.z + v1.w;
    float sq = v0.x*v0.x + v0.y*v0.y + v0.z*v0.z + v0.w*v0.w
             + v1.x*v1.x + v1.y*v1.y + v1.z*v1.z + v1.w*v1.w;
    #pragma unroll
    for (int o = 16; o; o >>= 1) {
        s  += __shfl_xor_sync(0xffffffffu, s,  o);
        sq += __shfl_xor_sync(0xffffffffu, sq, o);
    }
    float mu  = s * (1.0f / DIM);
    float var = sq * (1.0f / DIM) - mu * mu;
    float rs  = rsqrtf(var + 1e-5f);
    float4 w0 = *(const float4*)(gw + lane * 4);
    float4 w1 = *(const float4*)(gw + 128 + lane * 4);
    float4 b0 = *(const float4*)(gb + lane * 4);
    float4 b1 = *(const float4*)(gb + 128 + lane * 4);
    bf16* orow = out + (size_t)m * DIM;
    __nv_bfloat162 p;
    p = {__float2bfloat16((v0.x-mu)*rs*w0.x+b0.x), __float2bfloat16((v0.y-mu)*rs*w0.y+b0.y)};
    *(__nv_bfloat162*)(orow + lane*4)     = p;
    p = {__float2bfloat16((v0.z-mu)*rs*w0.z+b0.z), __float2bfloat16((v0.w-mu)*rs*w0.w+b0.w)};
    *(__nv_bfloat162*)(orow + lane*4 + 2) = p;
    p = {__float2bfloat16((v1.x-mu)*rs*w1.x+b1.x), __float2bfloat16((v1.y-mu)*rs*w1.y+b1.y)};
    *(__nv_bfloat162*)(orow + 128 + lane*4)     = p;
    p = {__float2bfloat16((v1.z-mu)*rs*w1.z+b1.z), __float2bfloat16((v1.w-mu)*rs*w1.w+b1.w)};
    *(__nv_bfloat162*)(orow + 128 + lane*4 + 2) = p;
}

// ============ persistent-B GEMM (K=256), bulk-copy A stream ===================
// 512 threads, warp grid 4(m)x4(n), warp tile 32x64.
// EPI: 0=+bias->bf16  1=+bias,GELU->bf16  2=+bias,remap,+res->f32
//      7=+bias,remap,+res->f32 AND fused LayerNorm->bf16 (requires grid.x==1)
#define PMB 0
#define PA_OFF 64
#define PA_SROW 144
#define PA_STAGE (128 * PA_SROW)
#define PB_SROW 528
#define PB_OFF (PA_OFF + 3 * PA_STAGE)      // 55360
#define RS_OFF (PB_OFF + 256 * PB_SROW)     // 190528 (rsum: 4x128 float2 = 4KB)
#define LNW_OFF (RS_OFF + 4096)             // gw/gb: 512 floats = 2KB
#define PSMEM (LNW_OFF + 2048)              // 196672

template<int EPI>
__global__ void __launch_bounds__(512, 1) pgemm(const bf16* __restrict__ A,
                                               const bf16* __restrict__ Bm,
                                               const float* __restrict__ bias,
                                               void* __restrict__ Cv,
                                               int M, int N, int lda, int ldb,
                                               const float* __restrict__ res,
                                               const float* __restrict__ lnw,
                                               const float* __restrict__ lnb,
                                               bf16* __restrict__ out2,
                                               int GY) {
    extern __shared__ __align__(128) char smem[];
    uint32_t sbase = smem_u32(smem);
    int tid = threadIdx.x;
    int warp = tid >> 5, lane = tid & 31;
    int bn = blockIdx.x, gy = blockIdx.y;
    int warpM = (warp & 3) * 32;
    int warpN = (warp >> 2) * 64;
    int r = lane >> 2, c = lane & 3;
    int mt = M >> 7;

    if (tid == 0) {
        mbar_init(sbase + PMB + 0, 128);
        mbar_init(sbase + PMB + 8, 128);
        mbar_init(sbase + PMB + 16, 128);
    }
    uint32_t sB = sbase + PB_OFF;
    {
        const bf16* Bbase = Bm + (size_t)(bn * 256) * ldb;
        #pragma unroll
        for (int rpt = 0; rpt < 16; rpt++) {
            int ch = tid + rpt * 512;
            int row = ch >> 5, col = ch & 31;
            cp16(sB + row * PB_SROW + col * 16, Bbase + (size_t)row * ldb + col * 8);
        }
    }
    if (EPI == 7 && tid < 256) {
        ((float*)(smem + LNW_OFF))[tid]       = lnw[tid];
        ((float*)(smem + LNW_OFF))[256 + tid] = lnb[tid];
    }
    cp_commit();
    __syncthreads();   // mbarrier init + LN weights visible

    uint32_t aoff = (uint32_t)((lane & 15) * PA_SROW + (lane >> 4) * 16);
    uint32_t boff = (uint32_t)(((lane & 7) + ((lane >> 4) << 3)) * PB_SROW
                               + ((lane & 8) ? 16 : 0));

    int ntiles = (mt - gy + GY - 1) / GY;
    int nj = ntiles * 4;

#define FILLA(s, j) do { \
    if (tid < 128) { \
        const bf16* Ab = A + (size_t)(gy + ((j) >> 2) * GY) * 128 * lda \
                         + ((j) & 3) * 64 + (size_t)tid * lda; \
        uint32_t mb = sbase + PMB + (s) * 8; \
        mbar_expect(mb, 128); \
        cpbulk(sbase + PA_OFF + (s) * PA_STAGE + tid * PA_SROW, Ab, 128, mb); \
    } \
} while (0)

    FILLA(0, 0);
    if (nj > 1) FILLA(1, 1);
    cp_wait<0>();

    for (int t = 0; t < ntiles; t++) {
        int bm = gy + t * GY;
        float acc[2][8][4];
        #pragma unroll
        for (int mi = 0; mi < 2; mi++)
            #pragma unroll
            for (int ni = 0; ni < 8; ni++)
                #pragma unroll
                for (int q = 0; q < 4; q++) acc[mi][ni][q] = 0.0f;

        #pragma unroll
        for (int s4 = 0; s4 < 4; s4++) {
            int j = t * 4 + s4;
            int st = j % 3;
            mbar_wait(sbase + PMB + st * 8, (uint32_t)((j / 3) & 1));
            __syncthreads();
            if (j + 2 < nj) FILLA((j + 2) % 3, j + 2);

            uint32_t As = sbase + PA_OFF + st * PA_STAGE;
            #pragma unroll
            for (int kk = 0; kk < 4; kk++) {
                int k16 = s4 * 4 + kk;
                uint32_t af[2][4], bfr[4][4];
                #pragma unroll
                for (int mi = 0; mi < 2; mi++)
                    ldsm4(af[mi], As + (uint32_t)((warpM + mi * 16) * PA_SROW + kk * 32) + aoff);
                #pragma unroll
                for (int p = 0; p < 4; p++)
                    ldsm4(bfr[p], sB + (uint32_t)((warpN + p * 16) * PB_SROW + k16 * 32) + boff);
                #pragma unroll
                for (int mi = 0; mi < 2; mi++)
                    #pragma unroll
                    for (int ni = 0; ni < 8; ni++)
                        mma_bf16(acc[mi][ni], af[mi], &bfr[ni >> 1][(ni & 1) * 2]);
            }
        }

        if (EPI == 7) {
            // pass 1: x1 = mma + bias + res (remap scatter), accumulate row sums
            float2* rsum = (float2*)(smem + RS_OFF);
            const float* gws = (const float*)(smem + LNW_OFF);
            const float* gbs = gws + 256;
            int wn = warp >> 2;
            #pragma unroll
            for (int mi = 0; mi < 2; mi++) {
                #pragma unroll
                for (int half = 0; half < 2; half++) {
                    int row = bm * 128 + warpM + mi * 16 + r + half * 8;
                    int orow = remap_row(row);
                    const float* rr = res + (size_t)orow * N;
                    float* cp = (float*)Cv + (size_t)orow * N;
                    float s = 0.0f, sq = 0.0f;
                    #pragma unroll
                    for (int ni = 0; ni < 8; ni++) {
                        int col = warpN + ni * 8 + 2 * c;
                        float v0 = acc[mi][ni][half * 2 + 0] + bias[col] + rr[col];
                        float v1 = acc[mi][ni][half * 2 + 1] + bias[col + 1] + rr[col + 1];
                        acc[mi][ni][half * 2 + 0] = v0;
                        acc[mi][ni][half * 2 + 1] = v1;
                        *(float2*)(cp + col) = make_float2(v0, v1);
                        s += v0 + v1;
                        sq += v0 * v0 + v1 * v1;
                    }
                    s  += __shfl_xor_sync(0xffffffffu, s, 1);
                    s  += __shfl_xor_sync(0xffffffffu, s, 2);
                    sq += __shfl_xor_sync(0xffffffffu, sq, 1);
                    sq += __shfl_xor_sync(0xffffffffu, sq, 2);
                    if ((lane & 3) == 0) {
                        int lr = warpM + mi * 16 + r + half * 8;
                        rsum[wn * 128 + lr] = make_float2(s, sq);
                    }
                }
            }
            __syncthreads();
            // pass 2: apply LN -> bf16 out2
            #pragma unroll
            for (int mi = 0; mi < 2; mi++) {
                #pragma unroll
                for (int half = 0; half < 2; half++) {
                    int lr = warpM + mi * 16 + r + half * 8;
                    float S = 0.0f, SQ = 0.0f;
                    #pragma unroll
                    for (int g = 0; g < 4; g++) {
                        float2 pp = rsum[g * 128 + lr];
                        S += pp.x; SQ += pp.y;
                    }
                    float mu  = S * (1.0f / 256.0f);
                    float var = SQ * (1.0f / 256.0f) - mu * mu;
                    float rsg = rsqrtf(var + 1e-5f);
                    int orow = remap_row(bm * 128 + lr);
                    bf16* op = out2 + (size_t)orow * 256;
                    #pragma unroll
                    for (int ni = 0; ni < 8; ni++) {
                        int col = warpN + ni * 8 + 2 * c;
                        float v0 = (acc[mi][ni][half * 2 + 0] - mu) * rsg * gws[col] + gbs[col];
                        float v1 = (acc[mi][ni][half * 2 + 1] - mu) * rsg * gws[col + 1] + gbs[col + 1];
                        __nv_bfloat162 pk = {__float2bfloat16(v0), __float2bfloat16(v1)};
                        *(__nv_bfloat162*)(op + col) = pk;
                    }
                }
            }
        } else {
            #pragma unroll
            for (int mi = 0; mi < 2; mi++) {
                #pragma unroll
                for (int half = 0; half < 2; half++) {
                    int row = bm * 128 + warpM + mi * 16 + r + half * 8;
                    int orow = row;
                    if (EPI == 2) orow = remap_row(row);
                    const float* rr = (EPI == 2) ? res + (size_t)orow * N : nullptr;
                    #pragma unroll
                    for (int ni = 0; ni < 8; ni++) {
                        int col = bn * 256 + warpN + ni * 8 + 2 * c;
                        float v0 = acc[mi][ni][half * 2 + 0] + bias[col];
                        float v1 = acc[mi][ni][half * 2 + 1] + bias[col + 1];
                        if (EPI == 1) {
                            v0 = 0.5f * v0 * (1.0f + erff(v0 * 0.70710678118654752f));
                            v1 = 0.5f * v1 * (1.0f + erff(v1 * 0.70710678118654752f));
                        }
                        if (EPI == 2) { v0 += rr[col]; v1 += rr[col + 1]; }
                        if (EPI == 0 || EPI == 1) {
                            bf16* cp = (bf16*)Cv + (size_t)orow * N;
                            __nv_bfloat162 pk = {__float2bfloat16(v0), __float2bfloat16(v1)};
                            *(__nv_bfloat162*)(cp + col) = pk;
                        } else {
                            float* cp = (float*)Cv + (size_t)orow * N;
                            *(float2*)(cp + col) = make_float2(v0, v1);
                        }
                    }
                }
            }
        }
    }
#undef FILLA
}

// ---------------- streaming GEMM (fc2, K=1024), cp16 (R11-proven) ------------
#define FSROW 144
#define FASTAGE (128 * FSROW)
#define FBSTAGE (256 * FSROW)
#define FSTAGEB (FASTAGE + FBSTAGE)
#define FNSTAGE 3
#define FSMEM (FNSTAGE * FSTAGEB)   // 165888

template<int EPI>
__global__ void __launch_bounds__(512, 1) bgemm(const bf16* __restrict__ A,
                                               const bf16* __restrict__ Bm,
                                               const float* __restrict__ bias,
                                               void* __restrict__ Cv,
                                               int M, int N, int K,
                                               const float* __restrict__ res) {
    extern __shared__ __align__(16) char smem[];
    uint32_t sbase = smem_u32(smem);
    int tid = threadIdx.x;
    int bn = blockIdx.x, bm = blockIdx.y;
    int warp = tid >> 5, lane = tid & 31;
    int warpM = (warp & 3) * 32;
    int warpN = (warp >> 2) * 64;
    int r = lane >> 2, c = lane & 3;

    int arw[2], acc_[2], brw[4], bcc[4];
    #pragma unroll
    for (int rpt = 0; rpt < 2; rpt++) {
        int ch = tid + rpt * 512;
        arw[rpt] = ch >> 3; acc_[rpt] = ch & 7;
    }
    #pragma unroll
    for (int rpt = 0; rpt < 4; rpt++) {
        int ch = tid + rpt * 512;
        brw[rpt] = ch >> 3; bcc[rpt] = ch & 7;
    }
    const bf16* Abase = A  + (size_t)(bm * 128) * K;
    const bf16* Bbase = Bm + (size_t)(bn * 256) * K;

    uint32_t aoff = (uint32_t)((lane & 15) * FSROW + (lane >> 4) * 16);
    uint32_t boff = (uint32_t)(((lane & 7) + ((lane >> 4) << 3)) * FSROW + ((lane & 8) ? 16 : 0));

    float acc[2][8][4];
    #pragma unroll
    for (int mi = 0; mi < 2; mi++)
        #pragma unroll
        for (int ni = 0; ni < 8; ni++)
            #pragma unroll
            for (int t = 0; t < 4; t++) acc[mi][ni][t] = 0.0f;

#define FILL(s, k0) do { \
    uint32_t ab = sbase + (s) * FSTAGEB; \
    uint32_t bb = ab + FASTAGE; \
    _Pragma("unroll") \
    for (int rpt = 0; rpt < 2; rpt++) \
        cp16(ab + arw[rpt] * FSROW + acc_[rpt] * 16, \
             Abase + (size_t)arw[rpt] * K + (k0) + acc_[rpt] * 8); \
    _Pragma("unroll") \
    for (int rpt = 0; rpt < 4; rpt++) \
        cp16(bb + brw[rpt] * FSROW + bcc[rpt] * 16, \
             Bbase + (size_t)brw[rpt] * K + (k0) + bcc[rpt] * 8); \
} while (0)

    int nk = K >> 6;
    FILL(0, 0);  cp_commit();
    FILL(1, 64); cp_commit();

    int stage = 0, fstage = 2;
    for (int i = 0; i < nk; i++) {
        cp_wait<1>();
        __syncthreads();
        if (i + 2 < nk) {
            FILL(fstage, (i + 2) * 64);
        }
        cp_commit();

        uint32_t Ab = sbase + stage * FSTAGEB;
        uint32_t Bb = Ab + FASTAGE;

        #pragma unroll
        for (int kk = 0; kk < 4; kk++) {
            uint32_t af[2][4], bfr[4][4];
            #pragma unroll
            for (int mi = 0; mi < 2; mi++)
                ldsm4(af[mi], Ab + (uint32_t)((warpM + mi * 16) * FSROW + kk * 32) + aoff);
            #pragma unroll
            for (int p = 0; p < 4; p++)
                ldsm4(bfr[p], Bb + (uint32_t)((warpN + p * 16) * FSROW + kk * 32) + boff);
            #pragma unroll
            for (int mi = 0; mi < 2; mi++)
                #pragma unroll
                for (int ni = 0; ni < 8; ni++)
                    mma_bf16(acc[mi][ni], af[mi], &bfr[ni >> 1][(ni & 1) * 2]);
        }

        stage = (stage + 1 == FNSTAGE) ? 0 : stage + 1;
        fstage = (fstage + 1 == FNSTAGE) ? 0 : fstage + 1;
    }

    #pragma unroll
    for (int mi = 0; mi < 2; mi++) {
        #pragma unroll
        for (int half = 0; half < 2; half++) {
            int row = bm * 128 + warpM + mi * 16 + r + half * 8;
            const float* rr = res + (size_t)row * N;
            #pragma unroll
            for (int ni = 0; ni < 8; ni++) {
                int col = bn * 256 + warpN + ni * 8 + 2 * c;
                float v0 = acc[mi][ni][half * 2 + 0] + bias[col] + rr[col];
                float v1 = acc[mi][ni][half * 2 + 1] + bias[col + 1] + rr[col + 1];
                float* cp = (float*)Cv + (size_t)row * N;
                *(float2*)(cp + col) = make_float2(v0, v1);
            }
        }
    }
#undef FILL
}

// ---------------- tensor-core windowed attention ------------------------------
__global__ void __launch_bounds__(256) attn_tc(const bf16* __restrict__ qkv,
                                               const bf16* __restrict__ comb,
                                               bf16* __restrict__ out) {
    __shared__ __align__(16) bf16 sQ[2][64 * 40];
    __shared__ __align__(16) bf16 sK[2][64 * 40];
    __shared__ __align__(16) bf16 sVT[2][32 * 72];
    __shared__ __align__(16) bf16 sB[2][64 * 72];

    int tid = threadIdx.x;
    int win = blockIdx.x;
    int hg  = blockIdx.y * 2;
    int w64 = win & 63;

    uint32_t* vz = (uint32_t*)sVT;
    for (int i = tid; i < 2 * 32 * 72 / 2; i += 256) vz[i] = 0;
    for (int i = tid; i < 600; i += 256) {
        int h = i / 300, rm = i % 300;
        int row = 49 + rm / 20, w = rm % 20;
        ((uint32_t*)sQ)[h * 1280 + row * 20 + w] = 0;
        ((uint32_t*)sK)[h * 1280 + row * 20 + w] = 0;
    }
    __syncthreads();

    for (int i = tid; i < 392; i += 256) {
        int h = i / 196, rm = i % 196;
        int tok = rm >> 2, ch = rm & 3;
        const bf16* src = qkv + (size_t)(win * 49 + tok) * 768 + (hg + h) * 32 + ch * 8;
        *(uint4*)((char*)sQ + h * 5120 + tok * 80 + ch * 16) = *(const uint4*)src;
        *(uint4*)((char*)sK + h * 5120 + tok * 80 + ch * 16) = *(const uint4*)(src + 256);
    }
    for (int i = tid; i < 1568; i += 256) {
        int h = i / 784, rm = i % 784;
        int tok = rm / 16, dp = (rm % 16) * 2;
        __nv_bfloat162 v = *(const __nv_bfloat162*)(qkv + (size_t)(win * 49 + tok) * 768
                                                    + 512 + (hg + h) * 32 + dp);
        *(bf16*)((char*)sVT + h * 4608 + dp * 144 + tok * 2)       = v.x;
        *(bf16*)((char*)sVT + h * 4608 + (dp + 1) * 144 + tok * 2) = v.y;
    }
    for (int i = tid; i < 1024; i += 256) {
        int h = i >> 9, rm = i & 511;
        int n = rm >> 3, ch = rm & 7;
        const bf16* src = comb + (((size_t)((w64 * 8 + hg + h) * 64 + n)) << 6) + ch * 8;
        *(uint4*)((char*)sB + h * 9216 + n * 144 + ch * 16) = *(const uint4*)src;
    }
    __syncthreads();

    int warp = tid >> 5, lane = tid & 31;
    int head = warp >> 2;
    int rowbase = (warp & 3) * 16;

    uint32_t Qb = smem_u32(sQ) + head * 5120;
    uint32_t Kb = smem_u32(sK) + head * 5120;
    uint32_t Vb = smem_u32(sVT) + head * 4608;
    uint32_t Bb = smem_u32(sB) + head * 9216;

    uint32_t aoff80  = (uint32_t)((lane & 15) * 80 + (lane >> 4) * 16);
    uint32_t aoff144 = (uint32_t)((lane & 15) * 144 + (lane >> 4) * 16);
    uint32_t boff80  = (uint32_t)(((lane & 7) + ((lane >> 4) << 3)) * 80 + ((lane & 8) ? 16 : 0));
    uint32_t boff144 = (uint32_t)(((lane & 7) + ((lane >> 4) << 3)) * 144 + ((lane & 8) ? 16 : 0));

    float sacc[8][4];
    #pragma unroll
    for (int ni = 0; ni < 8; ni++)
        #pragma unroll
        for (int t = 0; t < 4; t++) sacc[ni][t] = 0.0f;

    #pragma unroll
    for (int ks = 0; ks < 2; ks++) {
        uint32_t aq[4], bk[4][4];
        ldsm4(aq, Qb + (uint32_t)(rowbase * 80 + ks * 32) + aoff80);
        #pragma unroll
        for (int p = 0; p < 4; p++)
            ldsm4(bk[p], Kb + (uint32_t)(p * 16 * 80 + ks * 32) + boff80);
        #pragma unroll
        for (int ni = 0; ni < 8; ni++)
            mma_bf16(sacc[ni], aq, &bk[ni >> 1][(ni & 1) * 2]);
    }

    const float scale = 0.17677669529663687f;
    #pragma unroll
    for (int cg = 0; cg < 4; cg++) {
        uint32_t bb[4];
        ldsm4(bb, Bb + (uint32_t)(rowbase * 144 + cg * 32) + aoff144);
        float2 f;
        f = __bfloat1622float2(*(__nv_bfloat162*)&bb[0]);
        sacc[2*cg][0] = sacc[2*cg][0] * scale + f.x;
        sacc[2*cg][1] = sacc[2*cg][1] * scale + f.y;
        f = __bfloat1622float2(*(__nv_bfloat162*)&bb[1]);
        sacc[2*cg][2] = sacc[2*cg][2] * scale + f.x;
        sacc[2*cg][3] = sacc[2*cg][3] * scale + f.y;
        f = __bfloat1622float2(*(__nv_bfloat162*)&bb[2]);
        sacc[2*cg+1][0] = sacc[2*cg+1][0] * scale + f.x;
        sacc[2*cg+1][1] = sacc[2*cg+1][1] * scale + f.y;
        f = __bfloat1622float2(*(__nv_bfloat162*)&bb[3]);
        sacc[2*cg+1][2] = sacc[2*cg+1][2] * scale + f.x;
        sacc[2*cg+1][3] = sacc[2*cg+1][3] * scale + f.y;
    }

    #pragma unroll
    for (int hf = 0; hf < 2; hf++) {
        int i0 = hf * 2;
        float mx = -1e30f;
        #pragma unroll
        for (int ni = 0; ni < 8; ni++)
            mx = fmaxf(mx, fmaxf(sacc[ni][i0], sacc[ni][i0 + 1]));
        mx = fmaxf(mx, __shfl_xor_sync(0xffffffffu, mx, 1));
        mx = fmaxf(mx, __shfl_xor_sync(0xffffffffu, mx, 2));
        float sum = 0.0f;
        #pragma unroll
        for (int ni = 0; ni < 8; ni++) {
            float e0 = expf(sacc[ni][i0] - mx);
            float e1 = expf(sacc[ni][i0 + 1] - mx);
            sacc[ni][i0] = e0; sacc[ni][i0 + 1] = e1;
            sum += e0 + e1;
        }
        sum += __shfl_xor_sync(0xffffffffu, sum, 1);
        sum += __shfl_xor_sync(0xffffffffu, sum, 2);
        float inv = 1.0f / sum;
        #pragma unroll
        for (int ni = 0; ni < 8; ni++) {
            sacc[ni][i0] *= inv; sacc[ni][i0 + 1] *= inv;
        }
    }

    uint32_t pa[4][4];
    #pragma unroll
    for (int ks = 0; ks < 4; ks++) {
        pa[ks][0] = pack_bf16x2(sacc[2*ks][0],   sacc[2*ks][1]);
        pa[ks][1] = pack_bf16x2(sacc[2*ks][2],   sacc[2*ks][3]);
        pa[ks][2] = pack_bf16x2(sacc[2*ks+1][0], sacc[2*ks+1][1]);
        pa[ks][3] = pack_bf16x2(sacc[2*ks+1][2], sacc[2*ks+1][3]);
    }

    float oacc[4][4];
    #pragma unroll
    for (int ni = 0; ni < 4; ni++)
        #pragma unroll
        for (int t = 0; t < 4; t++) oacc[ni][t] = 0.0f;

    #pragma unroll
    for (int ks = 0; ks < 4; ks++) {
        uint32_t bv[2][4];
        #pragma unroll
        for (int p = 0; p < 2; p++)
            ldsm4(bv[p], Vb + (uint32_t)(p * 16 * 144 + ks * 32) + boff144);
        #pragma unroll
        for (int ni = 0; ni < 4; ni++)
            mma_bf16(oacc[ni], pa[ks], &bv[ni >> 1][(ni & 1) * 2]);
    }

    int gh = hg + head;
    int r0 = rowbase + (lane >> 2);
    #pragma unroll
    for (int ni = 0; ni < 4; ni++) {
        int col = gh * 32 + ni * 8 + (lane & 3) * 2;
        if (r0 < NTOK) {
            __nv_bfloat162 pk = {__float2bfloat16(oacc[ni][0]), __float2bfloat16(oacc[ni][1])};
            *(__nv_bfloat162*)(out + (size_t)(win * 49 + r0) * 256 + col) = pk;
        }
        if (r0 + 8 < NTOK) {
            __nv_bfloat162 pk = {__float2bfloat16(oacc[ni][2]), __float2bfloat16(oacc[ni][3])};
            *(__nv_bfloat162*)(out + (size_t)(win * 49 + r0 + 8) * 256 + col) = pk;
        }
    }
}

// ---------------- launcher ---------------------------------------------------
extern "C" void kernel_launch(void* const* d_in, const int* in_sizes, int n_in,
                              void* d_out, int out_size) {
    const float* x     = (const float*)d_in[0];
    const float* n1w   = (const float*)d_in[1];
    const float* n1b   = (const float*)d_in[2];
    const float* qkvw  = (const float*)d_in[3];
    const float* qkvb  = (const float*)d_in[4];
    const float* rpb   = (const float*)d_in[5];
    const float* projw = (const float*)d_in[6];
    const float* projb = (const float*)d_in[7];
    const float* n2w   = (const float*)d_in[8];
    const float* n2b   = (const float*)d_in[9];
    const float* fc1w  = (const float*)d_in[10];
    const float* fc1b  = (const float*)d_in[11];
    const float* fc2w  = (const float*)d_in[12];
    const float* fc2b  = (const float*)d_in[13];
    const int*   relix = (const int*)d_in[14];
    const float* amask = (const float*)d_in[15];
    float* out = (float*)d_out;

    bf16 *hwin, *qkv, *attn, *h2, *wqkv, *wproj, *wfc1, *wfc2, *comb;
    float *x1;
    cudaGetSymbolAddress((void**)&hwin, g_hwin);
    cudaGetSymbolAddress((void**)&qkv,  g_qkv);
    cudaGetSymbolAddress((void**)&attn, g_attn);
    cudaGetSymbolAddress((void**)&x1,   g_x1);
    cudaGetSymbolAddress((void**)&h2,   g_h2);
    cudaGetSymbolAddress((void**)&wqkv, g_wqkv);
    cudaGetSymbolAddress((void**)&wproj, g_wproj);
    cudaGetSymbolAddress((void**)&wfc1, g_wfc1);
    cudaGetSymbolAddress((void**)&wfc2, g_wfc2);
    cudaGetSymbolAddress((void**)&comb, g_comb);

    cudaFuncSetAttribute(pgemm<0>, cudaFuncAttributeMaxDynamicSharedMemorySize, PSMEM);
    cudaFuncSetAttribute(pgemm<1>, cudaFuncAttributeMaxDynamicSharedMemorySize, PSMEM);
    cudaFuncSetAttribute(pgemm<7>, cudaFuncAttributeMaxDynamicSharedMemorySize, PSMEM);
    cudaFuncSetAttribute(bgemm<3>, cudaFuncAttributeMaxDynamicSharedMemorySize, FSMEM);

    cvt4_kernel<<<dim3(DIM * HIDDEN / 4 / 256, 4), 256>>>(
        qkvw, wqkv, 3 * DIM * DIM,
        projw, wproj, DIM * DIM,
        fc1w, wfc1, HIDDEN * DIM,
        fc2w, wfc2, DIM * HIDDEN);
    comb_kernel<<<dim3(64, 8), 256>>>(rpb, relix, amask, comb);

    // 1. LN1 + shift + window-partition (bf16 out)
    ln_kernel<true><<<MTOT / 8, 256>>>(x, n1w, n1b, hwin);
    // 2. QKV GEMM (persistent-B, bulk A) -> bf16
    pgemm<0><<<dim3(3, 49), 512, PSMEM>>>(hwin, wqkv, qkvb, qkv, MTOT, 3 * DIM,
                                          DIM, DIM, nullptr, nullptr, nullptr,
                                          nullptr, 49);
    // 3. tensor-core windowed attention
    attn_tc<<<dim3(BZ * NWIN, 4), 256>>>(qkv, comb, attn);
    // 4. proj GEMM + remap + residual -> x1(f32) AND fused LN2 -> hwin(bf16)
    pgemm<7><<<dim3(1, 148), 512, PSMEM>>>(attn, wproj, projb, x1, MTOT, DIM,
                                           DIM, DIM, x, n2w, n2b, hwin, 148);
    // 5. FC1 + GELU (persistent-B) -> bf16
    pgemm<1><<<dim3(4, 37), 512, PSMEM>>>(hwin, wfc1, fc1b, h2, MTOT, HIDDEN,
                                          DIM, DIM, nullptr, nullptr, nullptr,
                                          nullptr, 37);
    // 6. FC2 + residual -> out (f32)  (streaming cp16, K=1024)
    bgemm<3><<<dim3(1, MTOT / 128), 512, FSMEM>>>(h2, wfc2, fc2b, out,
                                                  MTOT, DIM, HIDDEN, x1);
}